// round 12
// baseline (speedup 1.0000x reference)
#include <cuda_runtime.h>
#include <cstdint>

// Problem constants
#define NB 2
#define NS 2048
#define ND 1024
#define NH 16
#define NHD 64
#define NM (NB*NS)
#define SCALE_F 0.125f      // 64^-0.5

// Scratch (alloc-free rule: __device__ globals)
__device__ float g_q[NB*NH*NS*NHD];
__device__ float g_k[NB*NH*NS*NHD];
__device__ float g_v[NB*NH*NS*NHD];
__device__ float g_att[NB*NS*ND];

// ---------------------------------------------------------------------------
__device__ __forceinline__ uint32_t cvt_tf32(float f) {
    uint32_t r;
    asm("cvt.rna.tf32.f32 %0, %1;" : "=r"(r) : "f"(f));
    return r;
}

__device__ __forceinline__ void mma_tf32(float c[4],
                                         uint32_t a0, uint32_t a1,
                                         uint32_t a2, uint32_t a3,
                                         uint32_t b0, uint32_t b1) {
    asm volatile(
        "mma.sync.aligned.m16n8k8.row.col.f32.tf32.tf32.f32 "
        "{%0,%1,%2,%3}, {%4,%5,%6,%7}, {%8,%9}, {%0,%1,%2,%3};"
        : "+f"(c[0]), "+f"(c[1]), "+f"(c[2]), "+f"(c[3])
        : "r"(a0), "r"(a1), "r"(a2), "r"(a3), "r"(b0), "r"(b1));
}

// ---------------------------------------------------------------------------
// tf32 mma.sync GEMM. R11: vectorized B LDG (4x LDG.128 vs 16x LDG.32),
// B STS remap (4-way -> 2-way bank conflicts), hoisted fragment bases.
// MMA order/values unchanged -> numerics bit-identical to R9/R10.
// grid.z selects (W, bias, C) triple. CTA 128x128, BK=32, 8 warps.
// ---------------------------------------------------------------------------
#define SSTR 36

template<bool SCATTER>
__global__ void __launch_bounds__(256)
gemm_tc(const float* __restrict__ A,
        const float* __restrict__ W0, const float* __restrict__ b0, float* __restrict__ C0,
        const float* __restrict__ W1, const float* __restrict__ b1, float* __restrict__ C1,
        const float* __restrict__ W2, const float* __restrict__ b2, float* __restrict__ C2)
{
    constexpr int N = ND, K = ND;
    constexpr int BK = 32;
    constexpr int NCHUNK = K / BK;

    __shared__ uint32_t sA[128 * SSTR];
    __shared__ uint32_t sB[128 * SSTR];

    const float* W;
    const float* bias;
    float* C;
    if (blockIdx.z == 0)      { W = W0; bias = b0; C = C0; }
    else if (blockIdx.z == 1) { W = W1; bias = b1; C = C1; }
    else                      { W = W2; bias = b2; C = C2; }

    const int tid  = threadIdx.x;
    const int wid  = tid >> 5;
    const int lane = tid & 31;
    const int m0   = blockIdx.y * 128;
    const int n0   = blockIdx.x * 128;

    const int wm = (wid >> 2) * 64;
    const int wn = (wid & 3)  * 32;

    // B stage mapping: thread owns k = bk8 + 8p (p=0..3), n = bng..bng+3
    const int bk8 = tid & 7;           // 0..7
    const int bng = (tid >> 3) * 4;    // 0..124

    float4 a_pf[4];
    float4 b_pf[4];
    {
        #pragma unroll
        for (int i = 0; i < 4; ++i) {
            int lin = tid + 256*i;
            int r = lin >> 3, j = lin & 7;
            a_pf[i] = *reinterpret_cast<const float4*>(
                A + (size_t)(m0 + r) * K + j * 4);
        }
        #pragma unroll
        for (int p = 0; p < 4; ++p)
            b_pf[p] = *reinterpret_cast<const float4*>(
                W + (size_t)(bk8 + p*8) * N + n0 + bng);
    }

    float acc[16][4];
    #pragma unroll
    for (int t = 0; t < 16; ++t)
        #pragma unroll
        for (int e = 0; e < 4; ++e) acc[t][e] = 0.f;

    const int qrow = lane >> 2;
    const int qcol = lane & 3;

    for (int c = 0; c < NCHUNK; ++c) {
        if (c > 0) __syncthreads();

        #pragma unroll
        for (int i = 0; i < 4; ++i) {
            int lin = tid + 256*i;
            int r = lin >> 3, j = lin & 7;
            uint4 t;
            t.x = cvt_tf32(a_pf[i].x);
            t.y = cvt_tf32(a_pf[i].y);
            t.z = cvt_tf32(a_pf[i].z);
            t.w = cvt_tf32(a_pf[i].w);
            *reinterpret_cast<uint4*>(&sA[r * SSTR + j * 4]) = t;
        }
        #pragma unroll
        for (int p = 0; p < 4; ++p) {
            const float* f = reinterpret_cast<const float*>(&b_pf[p]);
            #pragma unroll
            for (int e = 0; e < 4; ++e)
                sB[(bng + e) * SSTR + bk8 + p*8] = cvt_tf32(f[e]);
        }

        if (c + 1 < NCHUNK) {
            const int k0n = (c + 1) * BK;
            #pragma unroll
            for (int i = 0; i < 4; ++i) {
                int lin = tid + 256*i;
                int r = lin >> 3, j = lin & 7;
                a_pf[i] = *reinterpret_cast<const float4*>(
                    A + (size_t)(m0 + r) * K + k0n + j * 4);
            }
            #pragma unroll
            for (int p = 0; p < 4; ++p)
                b_pf[p] = *reinterpret_cast<const float4*>(
                    W + (size_t)(k0n + bk8 + p*8) * N + n0 + bng);
        }

        __syncthreads();

        // hoisted fragment bases
        const uint32_t* aBase = &sA[(wm + qrow) * SSTR + qcol];
        const uint32_t* bBase = &sB[(wn + qrow) * SSTR + qcol];

        #pragma unroll
        for (int ks = 0; ks < 4; ++ks) {
            const int kbase = ks * 8;
            uint32_t af[4][4];
            #pragma unroll
            for (int i = 0; i < 4; ++i) {
                const uint32_t* p = aBase + i * (16 * SSTR) + kbase;
                af[i][0] = p[0];
                af[i][1] = p[8 * SSTR];
                af[i][2] = p[4];
                af[i][3] = p[8 * SSTR + 4];
            }
            uint32_t bf[4][2];
            #pragma unroll
            for (int j = 0; j < 4; ++j) {
                const uint32_t* p = bBase + j * (8 * SSTR) + kbase;
                bf[j][0] = p[0];
                bf[j][1] = p[4];
            }
            #pragma unroll
            for (int i = 0; i < 4; ++i)
                #pragma unroll
                for (int j = 0; j < 4; ++j)
                    mma_tf32(acc[i*4 + j],
                             af[i][0], af[i][1], af[i][2], af[i][3],
                             bf[j][0], bf[j][1]);
        }
    }

    #pragma unroll
    for (int i = 0; i < 4; ++i) {
        #pragma unroll
        for (int j = 0; j < 4; ++j) {
            const float* a4 = acc[i*4 + j];
            const int colg  = n0 + wn + j*8 + 2*qcol;
            const float2 bv = *reinterpret_cast<const float2*>(bias + colg);
            #pragma unroll
            for (int half = 0; half < 2; ++half) {
                const int m = m0 + wm + i*16 + qrow + half*8;
                float2 o;
                o.x = a4[half*2 + 0] + bv.x;
                o.y = a4[half*2 + 1] + bv.y;
                size_t idx;
                if (SCATTER) {
                    const int b = m >> 11;
                    const int s = m & (NS - 1);
                    const int h = colg >> 6;
                    const int hd = colg & 63;
                    idx = (((size_t)(b*NH + h))*NS + s)*NHD + hd;
                } else {
                    idx = (size_t)m * N + colg;
                }
                *reinterpret_cast<float2*>(C + idx) = o;
            }
        }
    }
}

// ---------------------------------------------------------------------------
// Tensor-core flash attention — UNCHANGED from R10 (current best).
// ---------------------------------------------------------------------------
#define AQ_STR   68
#define OFF_Q    0              // 128*68 = 8704
#define OFF_K0   8704           // 64*68  = 4352
#define OFF_K1   13056
#define OFF_V0   17408
#define OFF_V1   21760
#define SMEM_WORDS 26112        // *4 = 104448 B

__global__ void __launch_bounds__(256, 2)
attn_tc(const float* __restrict__ Q, const float* __restrict__ K,
        const float* __restrict__ V, float* __restrict__ O)
{
    extern __shared__ uint32_t sm[];
    uint32_t* sQ = sm + OFF_Q;

    const int tid  = threadIdx.x;
    const int wid  = tid >> 5;
    const int lane = tid & 31;
    const int qrow = lane >> 2;
    const int qcol = lane & 3;
    const int wm   = wid * 16;

    const int qt = (NS/128 - 1) - blockIdx.x;
    const int h  = blockIdx.y;
    const int b  = blockIdx.z;
    const int bh = b*NH + h;

    const float* Qb = Q + (size_t)bh * NS * NHD;
    const float* Kb = K + (size_t)bh * NS * NHD;
    const float* Vb = V + (size_t)bh * NS * NHD;

    const int kr = tid >> 4;
    const int kc = (tid & 15) * 4;
    const int vkey = tid & 63;
    const int vdg  = (tid >> 6) * 16;

    #pragma unroll
    for (int p = 0; p < 8; ++p) {
        int lin = tid + 256*p;
        int r = lin >> 4, c = (lin & 15) * 4;
        float4 qv = *reinterpret_cast<const float4*>(
            Qb + (size_t)(qt*128 + r)*NHD + c);
        uint32_t* d = &sQ[r * AQ_STR + c];
        d[0] = cvt_tf32(qv.x);
        d[1] = cvt_tf32(qv.y);
        d[2] = cvt_tf32(qv.z);
        d[3] = cvt_tf32(qv.w);
    }

    float o[8][4];
    #pragma unroll
    for (int nt = 0; nt < 8; ++nt)
        #pragma unroll
        for (int e = 0; e < 4; ++e) o[nt][e] = 0.f;
    float mrow[2] = {-1e30f, -1e30f};
    float lrow[2] = {0.f, 0.f};

    const int jmax = 2*qt + 1;

    float4 kreg[4], vreg[4];
    auto ldg_tile = [&](int jj) {
        const size_t rb = (size_t)jj * 64;
        #pragma unroll
        for (int p = 0; p < 4; ++p)
            kreg[p] = *reinterpret_cast<const float4*>(
                Kb + (rb + kr + p*16)*NHD + kc);
        #pragma unroll
        for (int g = 0; g < 4; ++g)
            vreg[g] = *reinterpret_cast<const float4*>(
                Vb + (rb + vkey)*NHD + vdg + g*4);
    };
    auto sts_tile = [&](int buf) {
        uint32_t* sK  = sm + OFF_K0 + buf * 4352;
        uint32_t* sVt = sm + OFF_V0 + buf * 4352;
        #pragma unroll
        for (int p = 0; p < 4; ++p) {
            uint4 t;
            t.x = cvt_tf32(kreg[p].x);
            t.y = cvt_tf32(kreg[p].y);
            t.z = cvt_tf32(kreg[p].z);
            t.w = cvt_tf32(kreg[p].w);
            *reinterpret_cast<uint4*>(&sK[(kr + p*16) * AQ_STR + kc]) = t;
        }
        #pragma unroll
        for (int g = 0; g < 4; ++g) {
            float f[4] = {vreg[g].x, vreg[g].y, vreg[g].z, vreg[g].w};
            #pragma unroll
            for (int e = 0; e < 4; ++e)
                sVt[(vdg + g*4 + e) * AQ_STR + vkey] = cvt_tf32(f[e]);
        }
    };

    ldg_tile(0);
    sts_tile(0);
    ldg_tile(1);
    __syncthreads();

    const int src1 = qrow*4 + (qcol >> 1);
    const int src2 = src1 + 2;
    const bool esel = (qcol & 1);

    for (int j = 0; j <= jmax; ++j) {
        const uint32_t* sK  = sm + OFF_K0 + (j & 1) * 4352;
        const uint32_t* sVt = sm + OFF_V0 + (j & 1) * 4352;

        if (j < jmax) {
            sts_tile((j + 1) & 1);
            if (j + 1 < jmax) ldg_tile(j + 2);
        }

        const bool active = (j*64 <= qt*128 + wm + 15);
        if (active) {
            float s[8][4];
            #pragma unroll
            for (int nt = 0; nt < 8; ++nt)
                #pragma unroll
                for (int e = 0; e < 4; ++e) s[nt][e] = 0.f;

            #pragma unroll
            for (int ks = 0; ks < 8; ++ks) {
                const uint32_t* qp = &sQ[(wm + qrow) * AQ_STR + ks*8 + qcol];
                uint32_t a0 = qp[0], a1 = qp[8*AQ_STR], a2 = qp[4], a3 = qp[8*AQ_STR + 4];
                #pragma unroll
                for (int nt = 0; nt < 8; ++nt) {
                    const int off = (nt*8 + qrow) * AQ_STR + ks*8 + qcol;
                    mma_tf32(s[nt], a0, a1, a2, a3, sK[off], sK[off + 4]);
                }
            }

            const bool need_mask = (j >= 2*qt);
            #pragma unroll
            for (int r = 0; r < 2; ++r) {
                const int rowg = qt*128 + wm + qrow + r*8;
                float mx = -1e30f;
                #pragma unroll
                for (int nt = 0; nt < 8; ++nt) {
                    const int colg = j*64 + nt*8 + 2*qcol;
                    float v0 = s[nt][r*2 + 0] * SCALE_F;
                    float v1 = s[nt][r*2 + 1] * SCALE_F;
                    if (need_mask) {
                        if (colg     > rowg) v0 = -1e30f;
                        if (colg + 1 > rowg) v1 = -1e30f;
                    }
                    s[nt][r*2 + 0] = v0;
                    s[nt][r*2 + 1] = v1;
                    mx = fmaxf(mx, fmaxf(v0, v1));
                }
                mx = fmaxf(mx, __shfl_xor_sync(0xffffffffu, mx, 1));
                mx = fmaxf(mx, __shfl_xor_sync(0xffffffffu, mx, 2));
                const float mn    = fmaxf(mrow[r], mx);
                const float alpha = __expf(mrow[r] - mn);
                mrow[r] = mn;
                float ls = 0.f;
                #pragma unroll
                for (int nt = 0; nt < 8; ++nt) {
                    float p0 = __expf(s[nt][r*2 + 0] - mn);
                    float p1 = __expf(s[nt][r*2 + 1] - mn);
                    s[nt][r*2 + 0] = p0;
                    s[nt][r*2 + 1] = p1;
                    ls += p0 + p1;
                }
                ls += __shfl_xor_sync(0xffffffffu, ls, 1);
                ls += __shfl_xor_sync(0xffffffffu, ls, 2);
                lrow[r] = lrow[r]*alpha + ls;
                #pragma unroll
                for (int nt = 0; nt < 8; ++nt) {
                    o[nt][r*2 + 0] *= alpha;
                    o[nt][r*2 + 1] *= alpha;
                }
            }

            #pragma unroll
            for (int ks = 0; ks < 8; ++ks) {
                uint32_t v0 = cvt_tf32(s[ks][0]);
                uint32_t v1 = cvt_tf32(s[ks][1]);
                uint32_t v2 = cvt_tf32(s[ks][2]);
                uint32_t v3 = cvt_tf32(s[ks][3]);
                uint32_t x0 = __shfl_sync(0xffffffffu, v0, src1);
                uint32_t x1 = __shfl_sync(0xffffffffu, v1, src1);
                uint32_t x2 = __shfl_sync(0xffffffffu, v2, src1);
                uint32_t x3 = __shfl_sync(0xffffffffu, v3, src1);
                uint32_t y0 = __shfl_sync(0xffffffffu, v0, src2);
                uint32_t y1 = __shfl_sync(0xffffffffu, v1, src2);
                uint32_t y2 = __shfl_sync(0xffffffffu, v2, src2);
                uint32_t y3 = __shfl_sync(0xffffffffu, v3, src2);
                uint32_t a0 = esel ? x1 : x0;
                uint32_t a1 = esel ? x3 : x2;
                uint32_t a2 = esel ? y1 : y0;
                uint32_t a3 = esel ? y3 : y2;
                #pragma unroll
                for (int nt = 0; nt < 8; ++nt) {
                    const int off = (nt*8 + qrow) * AQ_STR + ks*8 + qcol;
                    mma_tf32(o[nt], a0, a1, a2, a3, sVt[off], sVt[off + 4]);
                }
            }
        }

        __syncthreads();
    }

    #pragma unroll
    for (int r = 0; r < 2; ++r) {
        const float inv = 1.0f / lrow[r];
        const int rowg = qt*128 + wm + qrow + r*8;
        #pragma unroll
        for (int nt = 0; nt < 8; ++nt) {
            const int col = h*NHD + nt*8 + 2*qcol;
            float2 ov;
            ov.x = o[nt][r*2 + 0] * inv;
            ov.y = o[nt][r*2 + 1] * inv;
            *reinterpret_cast<float2*>(
                O + ((size_t)b*NS + rowg)*ND + col) = ov;
        }
    }
}

// ---------------------------------------------------------------------------
extern "C" void kernel_launch(void* const* d_in, const int* in_sizes, int n_in,
                              void* d_out, int out_size)
{
    const float* x  = (const float*)d_in[0];
    const float* wq = (const float*)d_in[1];
    const float* bq = (const float*)d_in[2];
    const float* wk = (const float*)d_in[3];
    const float* bk = (const float*)d_in[4];
    const float* wv = (const float*)d_in[5];
    const float* bv = (const float*)d_in[6];
    const float* wo = (const float*)d_in[7];
    const float* bo = (const float*)d_in[8];
    float* out = (float*)d_out;

    float *q, *k, *v, *att;
    cudaGetSymbolAddress((void**)&q,   g_q);
    cudaGetSymbolAddress((void**)&k,   g_k);
    cudaGetSymbolAddress((void**)&v,   g_v);
    cudaGetSymbolAddress((void**)&att, g_att);

    static bool attr_done = false;
    if (!attr_done) {
        cudaFuncSetAttribute(attn_tc,
            cudaFuncAttributeMaxDynamicSharedMemorySize, SMEM_WORDS * 4);
        attr_done = true;
    }

    dim3 qkv_grid(ND/128, NM/128, 3);   // (8, 32, 3) = 768 CTAs
    gemm_tc<true><<<qkv_grid, 256>>>(
        x, wq, bq, q, wk, bk, k, wv, bv, v);

    dim3 agrid(NS/128, NH, NB);         // (16, 16, 2)
    attn_tc<<<agrid, 256, SMEM_WORDS * 4>>>(q, k, v, att);

    dim3 ogrid(ND/128, NM/128, 1);
    gemm_tc<false><<<ogrid, 256>>>(
        att, wo, bo, out, wo, bo, out, wo, bo, out);
}

// round 13
// speedup vs baseline: 1.2461x; 1.2461x over previous
#include <cuda_runtime.h>
#include <cstdint>

// Problem constants
#define NB 2
#define NS 2048
#define ND 1024
#define NH 16
#define NHD 64
#define NM (NB*NS)
#define SCALE_F 0.125f      // 64^-0.5

// Scratch (alloc-free rule: __device__ globals)
__device__ float g_q[NB*NH*NS*NHD];
__device__ float g_k[NB*NH*NS*NHD];
__device__ float g_v[NB*NH*NS*NHD];
__device__ float g_att[NB*NS*ND];

// ---------------------------------------------------------------------------
__device__ __forceinline__ uint32_t cvt_tf32(float f) {
    uint32_t r;
    asm("cvt.rna.tf32.f32 %0, %1;" : "=r"(r) : "f"(f));
    return r;
}

__device__ __forceinline__ void mma_tf32(float c[4],
                                         uint32_t a0, uint32_t a1,
                                         uint32_t a2, uint32_t a3,
                                         uint32_t b0, uint32_t b1) {
    asm volatile(
        "mma.sync.aligned.m16n8k8.row.col.f32.tf32.tf32.f32 "
        "{%0,%1,%2,%3}, {%4,%5,%6,%7}, {%8,%9}, {%0,%1,%2,%3};"
        : "+f"(c[0]), "+f"(c[1]), "+f"(c[2]), "+f"(c[3])
        : "r"(a0), "r"(a1), "r"(a2), "r"(a3), "r"(b0), "r"(b1));
}

// ---------------------------------------------------------------------------
// tf32 mma.sync GEMM — R9/R10 body (coalesced B LDG restored).
// R12 delta: B STS vectorized to 4x STS.128 at the SAME addresses
// (conflict-free phases vs 4-way-conflicted scalar stores). Bit-identical.
// grid.z selects (W, bias, C) triple. CTA 128x128, BK=32, 8 warps.
// ---------------------------------------------------------------------------
#define SSTR 36

template<bool SCATTER>
__global__ void __launch_bounds__(256)
gemm_tc(const float* __restrict__ A,
        const float* __restrict__ W0, const float* __restrict__ b0, float* __restrict__ C0,
        const float* __restrict__ W1, const float* __restrict__ b1, float* __restrict__ C1,
        const float* __restrict__ W2, const float* __restrict__ b2, float* __restrict__ C2)
{
    constexpr int N = ND, K = ND;
    constexpr int BK = 32;
    constexpr int NCHUNK = K / BK;

    __shared__ uint32_t sA[128 * SSTR];
    __shared__ uint32_t sB[128 * SSTR];

    const float* W;
    const float* bias;
    float* C;
    if (blockIdx.z == 0)      { W = W0; bias = b0; C = C0; }
    else if (blockIdx.z == 1) { W = W1; bias = b1; C = C1; }
    else                      { W = W2; bias = b2; C = C2; }

    const int tid  = threadIdx.x;
    const int wid  = tid >> 5;
    const int lane = tid & 31;
    const int m0   = blockIdx.y * 128;
    const int n0   = blockIdx.x * 128;

    const int wm = (wid >> 2) * 64;
    const int wn = (wid & 3)  * 32;

    const int nloc = tid & 127;
    const int kb   = (tid >> 7) * 16;

    float4 a_pf[4];
    float  b_pf[16];
    {
        #pragma unroll
        for (int i = 0; i < 4; ++i) {
            int lin = tid + 256*i;
            int r = lin >> 3, j = lin & 7;
            a_pf[i] = *reinterpret_cast<const float4*>(
                A + (size_t)(m0 + r) * K + j * 4);
        }
        #pragma unroll
        for (int i = 0; i < 16; ++i)
            b_pf[i] = W[(size_t)(kb + i) * N + n0 + nloc];
    }

    float acc[16][4];
    #pragma unroll
    for (int t = 0; t < 16; ++t)
        #pragma unroll
        for (int e = 0; e < 4; ++e) acc[t][e] = 0.f;

    const int qrow = lane >> 2;
    const int qcol = lane & 3;

    for (int c = 0; c < NCHUNK; ++c) {
        if (c > 0) __syncthreads();

        #pragma unroll
        for (int i = 0; i < 4; ++i) {
            int lin = tid + 256*i;
            int r = lin >> 3, j = lin & 7;
            uint4 t;
            t.x = cvt_tf32(a_pf[i].x);
            t.y = cvt_tf32(a_pf[i].y);
            t.z = cvt_tf32(a_pf[i].z);
            t.w = cvt_tf32(a_pf[i].w);
            *reinterpret_cast<uint4*>(&sA[r * SSTR + j * 4]) = t;
        }
        // B STS: same addresses as scalar version, 4x STS.128
        #pragma unroll
        for (int g = 0; g < 4; ++g) {
            uint4 t;
            t.x = cvt_tf32(b_pf[g*4 + 0]);
            t.y = cvt_tf32(b_pf[g*4 + 1]);
            t.z = cvt_tf32(b_pf[g*4 + 2]);
            t.w = cvt_tf32(b_pf[g*4 + 3]);
            *reinterpret_cast<uint4*>(&sB[nloc * SSTR + kb + g*4]) = t;
        }

        if (c + 1 < NCHUNK) {
            const int k0n = (c + 1) * BK;
            #pragma unroll
            for (int i = 0; i < 4; ++i) {
                int lin = tid + 256*i;
                int r = lin >> 3, j = lin & 7;
                a_pf[i] = *reinterpret_cast<const float4*>(
                    A + (size_t)(m0 + r) * K + k0n + j * 4);
            }
            #pragma unroll
            for (int i = 0; i < 16; ++i)
                b_pf[i] = W[(size_t)(k0n + kb + i) * N + n0 + nloc];
        }

        __syncthreads();

        #pragma unroll
        for (int ks = 0; ks < 4; ++ks) {
            const int kbase = ks * 8 + qcol;
            uint32_t af[4][4];
            #pragma unroll
            for (int i = 0; i < 4; ++i) {
                const uint32_t* p = &sA[(wm + i*16 + qrow) * SSTR + kbase];
                af[i][0] = p[0];
                af[i][1] = p[8 * SSTR];
                af[i][2] = p[4];
                af[i][3] = p[8 * SSTR + 4];
            }
            uint32_t bf[4][2];
            #pragma unroll
            for (int j = 0; j < 4; ++j) {
                const uint32_t* p = &sB[(wn + j*8 + qrow) * SSTR + kbase];
                bf[j][0] = p[0];
                bf[j][1] = p[4];
            }
            #pragma unroll
            for (int i = 0; i < 4; ++i)
                #pragma unroll
                for (int j = 0; j < 4; ++j)
                    mma_tf32(acc[i*4 + j],
                             af[i][0], af[i][1], af[i][2], af[i][3],
                             bf[j][0], bf[j][1]);
        }
    }

    #pragma unroll
    for (int i = 0; i < 4; ++i) {
        #pragma unroll
        for (int j = 0; j < 4; ++j) {
            const float* a4 = acc[i*4 + j];
            const int colg  = n0 + wn + j*8 + 2*qcol;
            const float2 bv = *reinterpret_cast<const float2*>(bias + colg);
            #pragma unroll
            for (int half = 0; half < 2; ++half) {
                const int m = m0 + wm + i*16 + qrow + half*8;
                float2 o;
                o.x = a4[half*2 + 0] + bv.x;
                o.y = a4[half*2 + 1] + bv.y;
                size_t idx;
                if (SCATTER) {
                    const int b = m >> 11;
                    const int s = m & (NS - 1);
                    const int h = colg >> 6;
                    const int hd = colg & 63;
                    idx = (((size_t)(b*NH + h))*NS + s)*NHD + hd;
                } else {
                    idx = (size_t)m * N + colg;
                }
                *reinterpret_cast<float2*>(C + idx) = o;
            }
        }
    }
}

// ---------------------------------------------------------------------------
// Tensor-core flash attention — UNCHANGED from R10 (current best).
// ---------------------------------------------------------------------------
#define AQ_STR   68
#define OFF_Q    0              // 128*68 = 8704
#define OFF_K0   8704           // 64*68  = 4352
#define OFF_K1   13056
#define OFF_V0   17408
#define OFF_V1   21760
#define SMEM_WORDS 26112        // *4 = 104448 B

__global__ void __launch_bounds__(256, 2)
attn_tc(const float* __restrict__ Q, const float* __restrict__ K,
        const float* __restrict__ V, float* __restrict__ O)
{
    extern __shared__ uint32_t sm[];
    uint32_t* sQ = sm + OFF_Q;

    const int tid  = threadIdx.x;
    const int wid  = tid >> 5;
    const int lane = tid & 31;
    const int qrow = lane >> 2;
    const int qcol = lane & 3;
    const int wm   = wid * 16;

    const int qt = (NS/128 - 1) - blockIdx.x;
    const int h  = blockIdx.y;
    const int b  = blockIdx.z;
    const int bh = b*NH + h;

    const float* Qb = Q + (size_t)bh * NS * NHD;
    const float* Kb = K + (size_t)bh * NS * NHD;
    const float* Vb = V + (size_t)bh * NS * NHD;

    const int kr = tid >> 4;
    const int kc = (tid & 15) * 4;
    const int vkey = tid & 63;
    const int vdg  = (tid >> 6) * 16;

    #pragma unroll
    for (int p = 0; p < 8; ++p) {
        int lin = tid + 256*p;
        int r = lin >> 4, c = (lin & 15) * 4;
        float4 qv = *reinterpret_cast<const float4*>(
            Qb + (size_t)(qt*128 + r)*NHD + c);
        uint32_t* d = &sQ[r * AQ_STR + c];
        d[0] = cvt_tf32(qv.x);
        d[1] = cvt_tf32(qv.y);
        d[2] = cvt_tf32(qv.z);
        d[3] = cvt_tf32(qv.w);
    }

    float o[8][4];
    #pragma unroll
    for (int nt = 0; nt < 8; ++nt)
        #pragma unroll
        for (int e = 0; e < 4; ++e) o[nt][e] = 0.f;
    float mrow[2] = {-1e30f, -1e30f};
    float lrow[2] = {0.f, 0.f};

    const int jmax = 2*qt + 1;

    float4 kreg[4], vreg[4];
    auto ldg_tile = [&](int jj) {
        const size_t rb = (size_t)jj * 64;
        #pragma unroll
        for (int p = 0; p < 4; ++p)
            kreg[p] = *reinterpret_cast<const float4*>(
                Kb + (rb + kr + p*16)*NHD + kc);
        #pragma unroll
        for (int g = 0; g < 4; ++g)
            vreg[g] = *reinterpret_cast<const float4*>(
                Vb + (rb + vkey)*NHD + vdg + g*4);
    };
    auto sts_tile = [&](int buf) {
        uint32_t* sK  = sm + OFF_K0 + buf * 4352;
        uint32_t* sVt = sm + OFF_V0 + buf * 4352;
        #pragma unroll
        for (int p = 0; p < 4; ++p) {
            uint4 t;
            t.x = cvt_tf32(kreg[p].x);
            t.y = cvt_tf32(kreg[p].y);
            t.z = cvt_tf32(kreg[p].z);
            t.w = cvt_tf32(kreg[p].w);
            *reinterpret_cast<uint4*>(&sK[(kr + p*16) * AQ_STR + kc]) = t;
        }
        #pragma unroll
        for (int g = 0; g < 4; ++g) {
            float f[4] = {vreg[g].x, vreg[g].y, vreg[g].z, vreg[g].w};
            #pragma unroll
            for (int e = 0; e < 4; ++e)
                sVt[(vdg + g*4 + e) * AQ_STR + vkey] = cvt_tf32(f[e]);
        }
    };

    ldg_tile(0);
    sts_tile(0);
    ldg_tile(1);
    __syncthreads();

    const int src1 = qrow*4 + (qcol >> 1);
    const int src2 = src1 + 2;
    const bool esel = (qcol & 1);

    for (int j = 0; j <= jmax; ++j) {
        const uint32_t* sK  = sm + OFF_K0 + (j & 1) * 4352;
        const uint32_t* sVt = sm + OFF_V0 + (j & 1) * 4352;

        if (j < jmax) {
            sts_tile((j + 1) & 1);
            if (j + 1 < jmax) ldg_tile(j + 2);
        }

        const bool active = (j*64 <= qt*128 + wm + 15);
        if (active) {
            float s[8][4];
            #pragma unroll
            for (int nt = 0; nt < 8; ++nt)
                #pragma unroll
                for (int e = 0; e < 4; ++e) s[nt][e] = 0.f;

            #pragma unroll
            for (int ks = 0; ks < 8; ++ks) {
                const uint32_t* qp = &sQ[(wm + qrow) * AQ_STR + ks*8 + qcol];
                uint32_t a0 = qp[0], a1 = qp[8*AQ_STR], a2 = qp[4], a3 = qp[8*AQ_STR + 4];
                #pragma unroll
                for (int nt = 0; nt < 8; ++nt) {
                    const int off = (nt*8 + qrow) * AQ_STR + ks*8 + qcol;
                    mma_tf32(s[nt], a0, a1, a2, a3, sK[off], sK[off + 4]);
                }
            }

            const bool need_mask = (j >= 2*qt);
            #pragma unroll
            for (int r = 0; r < 2; ++r) {
                const int rowg = qt*128 + wm + qrow + r*8;
                float mx = -1e30f;
                #pragma unroll
                for (int nt = 0; nt < 8; ++nt) {
                    const int colg = j*64 + nt*8 + 2*qcol;
                    float v0 = s[nt][r*2 + 0] * SCALE_F;
                    float v1 = s[nt][r*2 + 1] * SCALE_F;
                    if (need_mask) {
                        if (colg     > rowg) v0 = -1e30f;
                        if (colg + 1 > rowg) v1 = -1e30f;
                    }
                    s[nt][r*2 + 0] = v0;
                    s[nt][r*2 + 1] = v1;
                    mx = fmaxf(mx, fmaxf(v0, v1));
                }
                mx = fmaxf(mx, __shfl_xor_sync(0xffffffffu, mx, 1));
                mx = fmaxf(mx, __shfl_xor_sync(0xffffffffu, mx, 2));
                const float mn    = fmaxf(mrow[r], mx);
                const float alpha = __expf(mrow[r] - mn);
                mrow[r] = mn;
                float ls = 0.f;
                #pragma unroll
                for (int nt = 0; nt < 8; ++nt) {
                    float p0 = __expf(s[nt][r*2 + 0] - mn);
                    float p1 = __expf(s[nt][r*2 + 1] - mn);
                    s[nt][r*2 + 0] = p0;
                    s[nt][r*2 + 1] = p1;
                    ls += p0 + p1;
                }
                ls += __shfl_xor_sync(0xffffffffu, ls, 1);
                ls += __shfl_xor_sync(0xffffffffu, ls, 2);
                lrow[r] = lrow[r]*alpha + ls;
                #pragma unroll
                for (int nt = 0; nt < 8; ++nt) {
                    o[nt][r*2 + 0] *= alpha;
                    o[nt][r*2 + 1] *= alpha;
                }
            }

            #pragma unroll
            for (int ks = 0; ks < 8; ++ks) {
                uint32_t v0 = cvt_tf32(s[ks][0]);
                uint32_t v1 = cvt_tf32(s[ks][1]);
                uint32_t v2 = cvt_tf32(s[ks][2]);
                uint32_t v3 = cvt_tf32(s[ks][3]);
                uint32_t x0 = __shfl_sync(0xffffffffu, v0, src1);
                uint32_t x1 = __shfl_sync(0xffffffffu, v1, src1);
                uint32_t x2 = __shfl_sync(0xffffffffu, v2, src1);
                uint32_t x3 = __shfl_sync(0xffffffffu, v3, src1);
                uint32_t y0 = __shfl_sync(0xffffffffu, v0, src2);
                uint32_t y1 = __shfl_sync(0xffffffffu, v1, src2);
                uint32_t y2 = __shfl_sync(0xffffffffu, v2, src2);
                uint32_t y3 = __shfl_sync(0xffffffffu, v3, src2);
                uint32_t a0 = esel ? x1 : x0;
                uint32_t a1 = esel ? x3 : x2;
                uint32_t a2 = esel ? y1 : y0;
                uint32_t a3 = esel ? y3 : y2;
                #pragma unroll
                for (int nt = 0; nt < 8; ++nt) {
                    const int off = (nt*8 + qrow) * AQ_STR + ks*8 + qcol;
                    mma_tf32(o[nt], a0, a1, a2, a3, sVt[off], sVt[off + 4]);
                }
            }
        }

        __syncthreads();
    }

    #pragma unroll
    for (int r = 0; r < 2; ++r) {
        const float inv = 1.0f / lrow[r];
        const int rowg = qt*128 + wm + qrow + r*8;
        #pragma unroll
        for (int nt = 0; nt < 8; ++nt) {
            const int col = h*NHD + nt*8 + 2*qcol;
            float2 ov;
            ov.x = o[nt][r*2 + 0] * inv;
            ov.y = o[nt][r*2 + 1] * inv;
            *reinterpret_cast<float2*>(
                O + ((size_t)b*NS + rowg)*ND + col) = ov;
        }
    }
}

// ---------------------------------------------------------------------------
extern "C" void kernel_launch(void* const* d_in, const int* in_sizes, int n_in,
                              void* d_out, int out_size)
{
    const float* x  = (const float*)d_in[0];
    const float* wq = (const float*)d_in[1];
    const float* bq = (const float*)d_in[2];
    const float* wk = (const float*)d_in[3];
    const float* bk = (const float*)d_in[4];
    const float* wv = (const float*)d_in[5];
    const float* bv = (const float*)d_in[6];
    const float* wo = (const float*)d_in[7];
    const float* bo = (const float*)d_in[8];
    float* out = (float*)d_out;

    float *q, *k, *v, *att;
    cudaGetSymbolAddress((void**)&q,   g_q);
    cudaGetSymbolAddress((void**)&k,   g_k);
    cudaGetSymbolAddress((void**)&v,   g_v);
    cudaGetSymbolAddress((void**)&att, g_att);

    static bool attr_done = false;
    if (!attr_done) {
        cudaFuncSetAttribute(attn_tc,
            cudaFuncAttributeMaxDynamicSharedMemorySize, SMEM_WORDS * 4);
        attr_done = true;
    }

    dim3 qkv_grid(ND/128, NM/128, 3);   // (8, 32, 3) = 768 CTAs
    gemm_tc<true><<<qkv_grid, 256>>>(
        x, wq, bq, q, wk, bk, k, wv, bv, v);

    dim3 agrid(NS/128, NH, NB);         // (16, 16, 2)
    attn_tc<<<agrid, 256, SMEM_WORDS * 4>>>(q, k, v, att);

    dim3 ogrid(ND/128, NM/128, 1);
    gemm_tc<false><<<ogrid, 256>>>(
        att, wo, bo, out, wo, bo, out, wo, bo, out);
}

// round 14
// speedup vs baseline: 1.4695x; 1.1792x over previous
#include <cuda_runtime.h>
#include <cuda_fp16.h>
#include <cstdint>

// Problem constants
#define NB 2
#define NS 2048
#define ND 1024
#define NH 16
#define NHD 64
#define NM (NB*NS)
#define SCALE_F 0.125f      // 64^-0.5

// Scratch (alloc-free rule: __device__ globals)
__device__ float g_q[NB*NH*NS*NHD];
__device__ float g_k[NB*NH*NS*NHD];
__device__ float g_v[NB*NH*NS*NHD];
__device__ float g_att[NB*NS*ND];

// ---------------------------------------------------------------------------
__device__ __forceinline__ uint32_t cvt_tf32(float f) {
    uint32_t r;
    asm("cvt.rna.tf32.f32 %0, %1;" : "=r"(r) : "f"(f));
    return r;
}

__device__ __forceinline__ uint32_t pack_h2(float lo, float hi) {
    __half2 h = __floats2half2_rn(lo, hi);
    return *reinterpret_cast<uint32_t*>(&h);
}

// tf32 m16n8k8 (used by attention — frozen)
__device__ __forceinline__ void mma_tf32(float c[4],
                                         uint32_t a0, uint32_t a1,
                                         uint32_t a2, uint32_t a3,
                                         uint32_t b0, uint32_t b1) {
    asm volatile(
        "mma.sync.aligned.m16n8k8.row.col.f32.tf32.tf32.f32 "
        "{%0,%1,%2,%3}, {%4,%5,%6,%7}, {%8,%9}, {%0,%1,%2,%3};"
        : "+f"(c[0]), "+f"(c[1]), "+f"(c[2]), "+f"(c[3])
        : "r"(a0), "r"(a1), "r"(a2), "r"(a3), "r"(b0), "r"(b1));
}

// fp16 m16n8k16, fp32 accumulate (GEMMs)
__device__ __forceinline__ void mma_fp16(float c[4],
                                         uint32_t a0, uint32_t a1,
                                         uint32_t a2, uint32_t a3,
                                         uint32_t b0, uint32_t b1) {
    asm volatile(
        "mma.sync.aligned.m16n8k16.row.col.f32.f16.f16.f32 "
        "{%0,%1,%2,%3}, {%4,%5,%6,%7}, {%8,%9}, {%0,%1,%2,%3};"
        : "+f"(c[0]), "+f"(c[1]), "+f"(c[2]), "+f"(c[3])
        : "r"(a0), "r"(a1), "r"(a2), "r"(a3), "r"(b0), "r"(b1));
}

// ---------------------------------------------------------------------------
// fp16 m16n8k16 GEMM: C[4096,1024] = A @ W + bias.
// CTA 128x128, K-chunk = 32 halves, 32 chunks, 8 warps (2M x 4N).
// smem words are half2 pairs; word stride 20 -> conflict-free frag loads
// (bank bases {0,20,8,28,16,4,24,12}+qcol cover all 32) and STS.
// grid.z selects (W, bias, C). SCATTER=true writes [B,H,S,HD].
// ---------------------------------------------------------------------------
#define GSTR 20   // word (half2) stride

template<bool SCATTER>
__global__ void __launch_bounds__(256)
gemm_fp16k(const float* __restrict__ A,
           const float* __restrict__ W0, const float* __restrict__ b0, float* __restrict__ C0,
           const float* __restrict__ W1, const float* __restrict__ b1, float* __restrict__ C1,
           const float* __restrict__ W2, const float* __restrict__ b2, float* __restrict__ C2)
{
    constexpr int N = ND, K = ND;
    constexpr int BK = 32;           // halves (fp32 elements) per chunk
    constexpr int NCHUNK = K / BK;   // 32

    __shared__ uint32_t sA[128 * GSTR];   // [m][kw], kw = k/2, half2 words
    __shared__ uint32_t sB[128 * GSTR];   // [n][kw]

    const float* W;
    const float* bias;
    float* C;
    if (blockIdx.z == 0)      { W = W0; bias = b0; C = C0; }
    else if (blockIdx.z == 1) { W = W1; bias = b1; C = C1; }
    else                      { W = W2; bias = b2; C = C2; }

    const int tid  = threadIdx.x;
    const int wid  = tid >> 5;
    const int lane = tid & 31;
    const int m0   = blockIdx.y * 128;
    const int n0   = blockIdx.x * 128;

    const int wm = (wid >> 2) * 64;
    const int wn = (wid & 3)  * 32;

    // A stage mapping: lin = tid + 256*i (i=0..1), r = lin>>2, j = lin&3
    //   thread loads float4 at k=8j and 8j+4 of row r -> 4 words at kw=4j..4j+3
    // B stage mapping: n = tid&127, kwb = (tid>>7)*8: 16 scalar k-loads
    const int nloc = tid & 127;
    const int kwb  = (tid >> 7) * 8;   // 0 or 8 (word index base)

    float4 a_pf[4];                     // 2 groups x 2 float4
    float  b_pf[16];

    auto ldg_chunk = [&](int k0) {      // k0 = fp32 element offset
        #pragma unroll
        for (int i = 0; i < 2; ++i) {
            int lin = tid + 256*i;
            int r = lin >> 2, j = lin & 3;
            const float* src = A + (size_t)(m0 + r) * K + k0 + j * 8;
            a_pf[i*2 + 0] = *reinterpret_cast<const float4*>(src);
            a_pf[i*2 + 1] = *reinterpret_cast<const float4*>(src + 4);
        }
        #pragma unroll
        for (int i = 0; i < 16; ++i)
            b_pf[i] = W[(size_t)(k0 + kwb*2 + i) * N + n0 + nloc];
    };
    auto sts_chunk = [&]() {
        #pragma unroll
        for (int i = 0; i < 2; ++i) {
            int lin = tid + 256*i;
            int r = lin >> 2, j = lin & 3;
            uint4 t;
            t.x = pack_h2(a_pf[i*2+0].x, a_pf[i*2+0].y);
            t.y = pack_h2(a_pf[i*2+0].z, a_pf[i*2+0].w);
            t.z = pack_h2(a_pf[i*2+1].x, a_pf[i*2+1].y);
            t.w = pack_h2(a_pf[i*2+1].z, a_pf[i*2+1].w);
            *reinterpret_cast<uint4*>(&sA[r * GSTR + j * 4]) = t;
        }
        {
            uint4 t0, t1;
            t0.x = pack_h2(b_pf[0],  b_pf[1]);
            t0.y = pack_h2(b_pf[2],  b_pf[3]);
            t0.z = pack_h2(b_pf[4],  b_pf[5]);
            t0.w = pack_h2(b_pf[6],  b_pf[7]);
            t1.x = pack_h2(b_pf[8],  b_pf[9]);
            t1.y = pack_h2(b_pf[10], b_pf[11]);
            t1.z = pack_h2(b_pf[12], b_pf[13]);
            t1.w = pack_h2(b_pf[14], b_pf[15]);
            *reinterpret_cast<uint4*>(&sB[nloc * GSTR + kwb])     = t0;
            *reinterpret_cast<uint4*>(&sB[nloc * GSTR + kwb + 4]) = t1;
        }
    };

    float acc[16][4];
    #pragma unroll
    for (int t = 0; t < 16; ++t)
        #pragma unroll
        for (int e = 0; e < 4; ++e) acc[t][e] = 0.f;

    const int qrow = lane >> 2;
    const int qcol = lane & 3;

    ldg_chunk(0);

    for (int c = 0; c < NCHUNK; ++c) {
        if (c > 0) __syncthreads();

        sts_chunk();

        if (c + 1 < NCHUNK) ldg_chunk((c + 1) * BK);

        __syncthreads();

        // 2 k16-steps per chunk
        #pragma unroll
        for (int ks = 0; ks < 2; ++ks) {
            const int kbase = ks * 8 + qcol;
            uint32_t af[4][4];
            #pragma unroll
            for (int i = 0; i < 4; ++i) {
                const uint32_t* p = &sA[(wm + i*16 + qrow) * GSTR + kbase];
                af[i][0] = p[0];
                af[i][1] = p[8 * GSTR];
                af[i][2] = p[4];
                af[i][3] = p[8 * GSTR + 4];
            }
            uint32_t bf[4][2];
            #pragma unroll
            for (int j = 0; j < 4; ++j) {
                const uint32_t* p = &sB[(wn + j*8 + qrow) * GSTR + kbase];
                bf[j][0] = p[0];
                bf[j][1] = p[4];
            }
            #pragma unroll
            for (int i = 0; i < 4; ++i)
                #pragma unroll
                for (int j = 0; j < 4; ++j)
                    mma_fp16(acc[i*4 + j],
                             af[i][0], af[i][1], af[i][2], af[i][3],
                             bf[j][0], bf[j][1]);
        }
    }

    // epilogue: bias + (optional) head-split scatter (C frag layout same as tf32)
    #pragma unroll
    for (int i = 0; i < 4; ++i) {
        #pragma unroll
        for (int j = 0; j < 4; ++j) {
            const float* a4 = acc[i*4 + j];
            const int colg  = n0 + wn + j*8 + 2*qcol;
            const float2 bv = *reinterpret_cast<const float2*>(bias + colg);
            #pragma unroll
            for (int half = 0; half < 2; ++half) {
                const int m = m0 + wm + i*16 + qrow + half*8;
                float2 o;
                o.x = a4[half*2 + 0] + bv.x;
                o.y = a4[half*2 + 1] + bv.y;
                size_t idx;
                if (SCATTER) {
                    const int b = m >> 11;
                    const int s = m & (NS - 1);
                    const int h = colg >> 6;
                    const int hd = colg & 63;
                    idx = (((size_t)(b*NH + h))*NS + s)*NHD + hd;
                } else {
                    idx = (size_t)m * N + colg;
                }
                *reinterpret_cast<float2*>(C + idx) = o;
            }
        }
    }
}

// ---------------------------------------------------------------------------
// Tensor-core flash attention — UNCHANGED from R10/R12 (current best).
// ---------------------------------------------------------------------------
#define AQ_STR   68
#define OFF_Q    0              // 128*68 = 8704
#define OFF_K0   8704           // 64*68  = 4352
#define OFF_K1   13056
#define OFF_V0   17408
#define OFF_V1   21760
#define SMEM_WORDS 26112        // *4 = 104448 B

__global__ void __launch_bounds__(256, 2)
attn_tc(const float* __restrict__ Q, const float* __restrict__ K,
        const float* __restrict__ V, float* __restrict__ O)
{
    extern __shared__ uint32_t sm[];
    uint32_t* sQ = sm + OFF_Q;

    const int tid  = threadIdx.x;
    const int wid  = tid >> 5;
    const int lane = tid & 31;
    const int qrow = lane >> 2;
    const int qcol = lane & 3;
    const int wm   = wid * 16;

    const int qt = (NS/128 - 1) - blockIdx.x;
    const int h  = blockIdx.y;
    const int b  = blockIdx.z;
    const int bh = b*NH + h;

    const float* Qb = Q + (size_t)bh * NS * NHD;
    const float* Kb = K + (size_t)bh * NS * NHD;
    const float* Vb = V + (size_t)bh * NS * NHD;

    const int kr = tid >> 4;
    const int kc = (tid & 15) * 4;
    const int vkey = tid & 63;
    const int vdg  = (tid >> 6) * 16;

    #pragma unroll
    for (int p = 0; p < 8; ++p) {
        int lin = tid + 256*p;
        int r = lin >> 4, c = (lin & 15) * 4;
        float4 qv = *reinterpret_cast<const float4*>(
            Qb + (size_t)(qt*128 + r)*NHD + c);
        uint32_t* d = &sQ[r * AQ_STR + c];
        d[0] = cvt_tf32(qv.x);
        d[1] = cvt_tf32(qv.y);
        d[2] = cvt_tf32(qv.z);
        d[3] = cvt_tf32(qv.w);
    }

    float o[8][4];
    #pragma unroll
    for (int nt = 0; nt < 8; ++nt)
        #pragma unroll
        for (int e = 0; e < 4; ++e) o[nt][e] = 0.f;
    float mrow[2] = {-1e30f, -1e30f};
    float lrow[2] = {0.f, 0.f};

    const int jmax = 2*qt + 1;

    float4 kreg[4], vreg[4];
    auto ldg_tile = [&](int jj) {
        const size_t rb = (size_t)jj * 64;
        #pragma unroll
        for (int p = 0; p < 4; ++p)
            kreg[p] = *reinterpret_cast<const float4*>(
                Kb + (rb + kr + p*16)*NHD + kc);
        #pragma unroll
        for (int g = 0; g < 4; ++g)
            vreg[g] = *reinterpret_cast<const float4*>(
                Vb + (rb + vkey)*NHD + vdg + g*4);
    };
    auto sts_tile = [&](int buf) {
        uint32_t* sK  = sm + OFF_K0 + buf * 4352;
        uint32_t* sVt = sm + OFF_V0 + buf * 4352;
        #pragma unroll
        for (int p = 0; p < 4; ++p) {
            uint4 t;
            t.x = cvt_tf32(kreg[p].x);
            t.y = cvt_tf32(kreg[p].y);
            t.z = cvt_tf32(kreg[p].z);
            t.w = cvt_tf32(kreg[p].w);
            *reinterpret_cast<uint4*>(&sK[(kr + p*16) * AQ_STR + kc]) = t;
        }
        #pragma unroll
        for (int g = 0; g < 4; ++g) {
            float f[4] = {vreg[g].x, vreg[g].y, vreg[g].z, vreg[g].w};
            #pragma unroll
            for (int e = 0; e < 4; ++e)
                sVt[(vdg + g*4 + e) * AQ_STR + vkey] = cvt_tf32(f[e]);
        }
    };

    ldg_tile(0);
    sts_tile(0);
    ldg_tile(1);
    __syncthreads();

    const int src1 = qrow*4 + (qcol >> 1);
    const int src2 = src1 + 2;
    const bool esel = (qcol & 1);

    for (int j = 0; j <= jmax; ++j) {
        const uint32_t* sK  = sm + OFF_K0 + (j & 1) * 4352;
        const uint32_t* sVt = sm + OFF_V0 + (j & 1) * 4352;

        if (j < jmax) {
            sts_tile((j + 1) & 1);
            if (j + 1 < jmax) ldg_tile(j + 2);
        }

        const bool active = (j*64 <= qt*128 + wm + 15);
        if (active) {
            float s[8][4];
            #pragma unroll
            for (int nt = 0; nt < 8; ++nt)
                #pragma unroll
                for (int e = 0; e < 4; ++e) s[nt][e] = 0.f;

            #pragma unroll
            for (int ks = 0; ks < 8; ++ks) {
                const uint32_t* qp = &sQ[(wm + qrow) * AQ_STR + ks*8 + qcol];
                uint32_t a0 = qp[0], a1 = qp[8*AQ_STR], a2 = qp[4], a3 = qp[8*AQ_STR + 4];
                #pragma unroll
                for (int nt = 0; nt < 8; ++nt) {
                    const int off = (nt*8 + qrow) * AQ_STR + ks*8 + qcol;
                    mma_tf32(s[nt], a0, a1, a2, a3, sK[off], sK[off + 4]);
                }
            }

            const bool need_mask = (j >= 2*qt);
            #pragma unroll
            for (int r = 0; r < 2; ++r) {
                const int rowg = qt*128 + wm + qrow + r*8;
                float mx = -1e30f;
                #pragma unroll
                for (int nt = 0; nt < 8; ++nt) {
                    const int colg = j*64 + nt*8 + 2*qcol;
                    float v0 = s[nt][r*2 + 0] * SCALE_F;
                    float v1 = s[nt][r*2 + 1] * SCALE_F;
                    if (need_mask) {
                        if (colg     > rowg) v0 = -1e30f;
                        if (colg + 1 > rowg) v1 = -1e30f;
                    }
                    s[nt][r*2 + 0] = v0;
                    s[nt][r*2 + 1] = v1;
                    mx = fmaxf(mx, fmaxf(v0, v1));
                }
                mx = fmaxf(mx, __shfl_xor_sync(0xffffffffu, mx, 1));
                mx = fmaxf(mx, __shfl_xor_sync(0xffffffffu, mx, 2));
                const float mn    = fmaxf(mrow[r], mx);
                const float alpha = __expf(mrow[r] - mn);
                mrow[r] = mn;
                float ls = 0.f;
                #pragma unroll
                for (int nt = 0; nt < 8; ++nt) {
                    float p0 = __expf(s[nt][r*2 + 0] - mn);
                    float p1 = __expf(s[nt][r*2 + 1] - mn);
                    s[nt][r*2 + 0] = p0;
                    s[nt][r*2 + 1] = p1;
                    ls += p0 + p1;
                }
                ls += __shfl_xor_sync(0xffffffffu, ls, 1);
                ls += __shfl_xor_sync(0xffffffffu, ls, 2);
                lrow[r] = lrow[r]*alpha + ls;
                #pragma unroll
                for (int nt = 0; nt < 8; ++nt) {
                    o[nt][r*2 + 0] *= alpha;
                    o[nt][r*2 + 1] *= alpha;
                }
            }

            #pragma unroll
            for (int ks = 0; ks < 8; ++ks) {
                uint32_t v0 = cvt_tf32(s[ks][0]);
                uint32_t v1 = cvt_tf32(s[ks][1]);
                uint32_t v2 = cvt_tf32(s[ks][2]);
                uint32_t v3 = cvt_tf32(s[ks][3]);
                uint32_t x0 = __shfl_sync(0xffffffffu, v0, src1);
                uint32_t x1 = __shfl_sync(0xffffffffu, v1, src1);
                uint32_t x2 = __shfl_sync(0xffffffffu, v2, src1);
                uint32_t x3 = __shfl_sync(0xffffffffu, v3, src1);
                uint32_t y0 = __shfl_sync(0xffffffffu, v0, src2);
                uint32_t y1 = __shfl_sync(0xffffffffu, v1, src2);
                uint32_t y2 = __shfl_sync(0xffffffffu, v2, src2);
                uint32_t y3 = __shfl_sync(0xffffffffu, v3, src2);
                uint32_t a0 = esel ? x1 : x0;
                uint32_t a1 = esel ? x3 : x2;
                uint32_t a2 = esel ? y1 : y0;
                uint32_t a3 = esel ? y3 : y2;
                #pragma unroll
                for (int nt = 0; nt < 8; ++nt) {
                    const int off = (nt*8 + qrow) * AQ_STR + ks*8 + qcol;
                    mma_tf32(o[nt], a0, a1, a2, a3, sVt[off], sVt[off + 4]);
                }
            }
        }

        __syncthreads();
    }

    #pragma unroll
    for (int r = 0; r < 2; ++r) {
        const float inv = 1.0f / lrow[r];
        const int rowg = qt*128 + wm + qrow + r*8;
        #pragma unroll
        for (int nt = 0; nt < 8; ++nt) {
            const int col = h*NHD + nt*8 + 2*qcol;
            float2 ov;
            ov.x = o[nt][r*2 + 0] * inv;
            ov.y = o[nt][r*2 + 1] * inv;
            *reinterpret_cast<float2*>(
                O + ((size_t)b*NS + rowg)*ND + col) = ov;
        }
    }
}

// ---------------------------------------------------------------------------
extern "C" void kernel_launch(void* const* d_in, const int* in_sizes, int n_in,
                              void* d_out, int out_size)
{
    const float* x  = (const float*)d_in[0];
    const float* wq = (const float*)d_in[1];
    const float* bq = (const float*)d_in[2];
    const float* wk = (const float*)d_in[3];
    const float* bk = (const float*)d_in[4];
    const float* wv = (const float*)d_in[5];
    const float* bv = (const float*)d_in[6];
    const float* wo = (const float*)d_in[7];
    const float* bo = (const float*)d_in[8];
    float* out = (float*)d_out;

    float *q, *k, *v, *att;
    cudaGetSymbolAddress((void**)&q,   g_q);
    cudaGetSymbolAddress((void**)&k,   g_k);
    cudaGetSymbolAddress((void**)&v,   g_v);
    cudaGetSymbolAddress((void**)&att, g_att);

    static bool attr_done = false;
    if (!attr_done) {
        cudaFuncSetAttribute(attn_tc,
            cudaFuncAttributeMaxDynamicSharedMemorySize, SMEM_WORDS * 4);
        attr_done = true;
    }

    dim3 qkv_grid(ND/128, NM/128, 3);   // (8, 32, 3) = 768 CTAs
    gemm_fp16k<true><<<qkv_grid, 256>>>(
        x, wq, bq, q, wk, bk, k, wv, bv, v);

    dim3 agrid(NS/128, NH, NB);         // (16, 16, 2)
    attn_tc<<<agrid, 256, SMEM_WORDS * 4>>>(q, k, v, att);

    dim3 ogrid(ND/128, NM/128, 1);
    gemm_fp16k<false><<<ogrid, 256>>>(
        att, wo, bo, out, wo, bo, out, wo, bo, out);
}

// round 15
// speedup vs baseline: 1.8720x; 1.2739x over previous
#include <cuda_runtime.h>
#include <cuda_fp16.h>
#include <cstdint>

// Problem constants
#define NB 2
#define NS 2048
#define ND 1024
#define NH 16
#define NHD 64
#define NM (NB*NS)
#define SCALE_F 0.125f      // 64^-0.5

// Scratch (alloc-free rule: __device__ globals)
__device__ float g_q[NB*NH*NS*NHD];
__device__ float g_k[NB*NH*NS*NHD];
__device__ float g_v[NB*NH*NS*NHD];
__device__ float g_att[NB*NS*ND];

// ---------------------------------------------------------------------------
__device__ __forceinline__ uint32_t pack_h2(float lo, float hi) {
    __half2 h = __floats2half2_rn(lo, hi);
    return *reinterpret_cast<uint32_t*>(&h);
}

// fp16 m16n8k16, fp32 accumulate
__device__ __forceinline__ void mma_fp16(float c[4],
                                         uint32_t a0, uint32_t a1,
                                         uint32_t a2, uint32_t a3,
                                         uint32_t b0, uint32_t b1) {
    asm volatile(
        "mma.sync.aligned.m16n8k16.row.col.f32.f16.f16.f32 "
        "{%0,%1,%2,%3}, {%4,%5,%6,%7}, {%8,%9}, {%0,%1,%2,%3};"
        : "+f"(c[0]), "+f"(c[1]), "+f"(c[2]), "+f"(c[3])
        : "r"(a0), "r"(a1), "r"(a2), "r"(a3), "r"(b0), "r"(b1));
}

// ---------------------------------------------------------------------------
// fp16 m16n8k16 GEMM — UNCHANGED from R13 (passing, 133.7us QKV).
// ---------------------------------------------------------------------------
#define GSTR 20   // word (half2) stride

template<bool SCATTER>
__global__ void __launch_bounds__(256)
gemm_fp16k(const float* __restrict__ A,
           const float* __restrict__ W0, const float* __restrict__ b0, float* __restrict__ C0,
           const float* __restrict__ W1, const float* __restrict__ b1, float* __restrict__ C1,
           const float* __restrict__ W2, const float* __restrict__ b2, float* __restrict__ C2)
{
    constexpr int N = ND, K = ND;
    constexpr int BK = 32;
    constexpr int NCHUNK = K / BK;

    __shared__ uint32_t sA[128 * GSTR];
    __shared__ uint32_t sB[128 * GSTR];

    const float* W;
    const float* bias;
    float* C;
    if (blockIdx.z == 0)      { W = W0; bias = b0; C = C0; }
    else if (blockIdx.z == 1) { W = W1; bias = b1; C = C1; }
    else                      { W = W2; bias = b2; C = C2; }

    const int tid  = threadIdx.x;
    const int wid  = tid >> 5;
    const int lane = tid & 31;
    const int m0   = blockIdx.y * 128;
    const int n0   = blockIdx.x * 128;

    const int wm = (wid >> 2) * 64;
    const int wn = (wid & 3)  * 32;

    const int nloc = tid & 127;
    const int kwb  = (tid >> 7) * 8;

    float4 a_pf[4];
    float  b_pf[16];

    auto ldg_chunk = [&](int k0) {
        #pragma unroll
        for (int i = 0; i < 2; ++i) {
            int lin = tid + 256*i;
            int r = lin >> 2, j = lin & 3;
            const float* src = A + (size_t)(m0 + r) * K + k0 + j * 8;
            a_pf[i*2 + 0] = *reinterpret_cast<const float4*>(src);
            a_pf[i*2 + 1] = *reinterpret_cast<const float4*>(src + 4);
        }
        #pragma unroll
        for (int i = 0; i < 16; ++i)
            b_pf[i] = W[(size_t)(k0 + kwb*2 + i) * N + n0 + nloc];
    };
    auto sts_chunk = [&]() {
        #pragma unroll
        for (int i = 0; i < 2; ++i) {
            int lin = tid + 256*i;
            int r = lin >> 2, j = lin & 3;
            uint4 t;
            t.x = pack_h2(a_pf[i*2+0].x, a_pf[i*2+0].y);
            t.y = pack_h2(a_pf[i*2+0].z, a_pf[i*2+0].w);
            t.z = pack_h2(a_pf[i*2+1].x, a_pf[i*2+1].y);
            t.w = pack_h2(a_pf[i*2+1].z, a_pf[i*2+1].w);
            *reinterpret_cast<uint4*>(&sA[r * GSTR + j * 4]) = t;
        }
        {
            uint4 t0, t1;
            t0.x = pack_h2(b_pf[0],  b_pf[1]);
            t0.y = pack_h2(b_pf[2],  b_pf[3]);
            t0.z = pack_h2(b_pf[4],  b_pf[5]);
            t0.w = pack_h2(b_pf[6],  b_pf[7]);
            t1.x = pack_h2(b_pf[8],  b_pf[9]);
            t1.y = pack_h2(b_pf[10], b_pf[11]);
            t1.z = pack_h2(b_pf[12], b_pf[13]);
            t1.w = pack_h2(b_pf[14], b_pf[15]);
            *reinterpret_cast<uint4*>(&sB[nloc * GSTR + kwb])     = t0;
            *reinterpret_cast<uint4*>(&sB[nloc * GSTR + kwb + 4]) = t1;
        }
    };

    float acc[16][4];
    #pragma unroll
    for (int t = 0; t < 16; ++t)
        #pragma unroll
        for (int e = 0; e < 4; ++e) acc[t][e] = 0.f;

    const int qrow = lane >> 2;
    const int qcol = lane & 3;

    ldg_chunk(0);

    for (int c = 0; c < NCHUNK; ++c) {
        if (c > 0) __syncthreads();

        sts_chunk();

        if (c + 1 < NCHUNK) ldg_chunk((c + 1) * BK);

        __syncthreads();

        #pragma unroll
        for (int ks = 0; ks < 2; ++ks) {
            const int kbase = ks * 8 + qcol;
            uint32_t af[4][4];
            #pragma unroll
            for (int i = 0; i < 4; ++i) {
                const uint32_t* p = &sA[(wm + i*16 + qrow) * GSTR + kbase];
                af[i][0] = p[0];
                af[i][1] = p[8 * GSTR];
                af[i][2] = p[4];
                af[i][3] = p[8 * GSTR + 4];
            }
            uint32_t bf[4][2];
            #pragma unroll
            for (int j = 0; j < 4; ++j) {
                const uint32_t* p = &sB[(wn + j*8 + qrow) * GSTR + kbase];
                bf[j][0] = p[0];
                bf[j][1] = p[4];
            }
            #pragma unroll
            for (int i = 0; i < 4; ++i)
                #pragma unroll
                for (int j = 0; j < 4; ++j)
                    mma_fp16(acc[i*4 + j],
                             af[i][0], af[i][1], af[i][2], af[i][3],
                             bf[j][0], bf[j][1]);
        }
    }

    #pragma unroll
    for (int i = 0; i < 4; ++i) {
        #pragma unroll
        for (int j = 0; j < 4; ++j) {
            const float* a4 = acc[i*4 + j];
            const int colg  = n0 + wn + j*8 + 2*qcol;
            const float2 bv = *reinterpret_cast<const float2*>(bias + colg);
            #pragma unroll
            for (int half = 0; half < 2; ++half) {
                const int m = m0 + wm + i*16 + qrow + half*8;
                float2 o;
                o.x = a4[half*2 + 0] + bv.x;
                o.y = a4[half*2 + 1] + bv.y;
                size_t idx;
                if (SCATTER) {
                    const int b = m >> 11;
                    const int s = m & (NS - 1);
                    const int h = colg >> 6;
                    const int hd = colg & 63;
                    idx = (((size_t)(b*NH + h))*NS + s)*NHD + hd;
                } else {
                    idx = (size_t)m * N + colg;
                }
                *reinterpret_cast<float2*>(C + idx) = o;
            }
        }
    }
}

// ---------------------------------------------------------------------------
// fp16 tensor-core flash attention, causal.
// R14: all MMAs m16n8k16 fp16 (fp32 accum). P C-fragment feeds PV A-fragment
// via pure register packs (no shuffle/smem relayout). Double-buffered K/V,
// one __syncthreads per key-tile iteration. smem 55296 B.
// ---------------------------------------------------------------------------
#define QSTR   36               // half2-word stride
#define AOFF_Q 0                // 128*36 = 4608 words
#define KTILE  (64*36)          // 2304 words
#define AOFF_K0 4608
#define AOFF_V0 9216
#define ASMEM_WORDS 13824       // *4 = 55296 B

__global__ void __launch_bounds__(256, 2)
attn_tc(const float* __restrict__ Q, const float* __restrict__ K,
        const float* __restrict__ V, float* __restrict__ O)
{
    extern __shared__ uint32_t sm[];
    uint32_t* sQ = sm + AOFF_Q;

    const int tid  = threadIdx.x;
    const int wid  = tid >> 5;
    const int lane = tid & 31;
    const int qrow = lane >> 2;   // 0..7
    const int qcol = lane & 3;    // 0..3
    const int wm   = wid * 16;

    const int qt = (NS/128 - 1) - blockIdx.x;   // largest-work tiles first
    const int h  = blockIdx.y;
    const int b  = blockIdx.z;
    const int bh = b*NH + h;

    const float* Qb = Q + (size_t)bh * NS * NHD;
    const float* Kb = K + (size_t)bh * NS * NHD;
    const float* Vb = V + (size_t)bh * NS * NHD;

    const int kr = tid >> 4;         // 0..15
    const int kc = (tid & 15) * 4;   // 0..60
    const int vkey = tid & 63;
    const int vdg  = (tid >> 6) * 16;

    // ---- load Q tile as half2 words, [row][dw] ----
    #pragma unroll
    for (int p = 0; p < 8; ++p) {
        int lin = tid + 256*p;
        int r = lin >> 4, c = (lin & 15) * 4;
        float4 qv = *reinterpret_cast<const float4*>(
            Qb + (size_t)(qt*128 + r)*NHD + c);
        uint2 t;
        t.x = pack_h2(qv.x, qv.y);
        t.y = pack_h2(qv.z, qv.w);
        *reinterpret_cast<uint2*>(&sQ[r * QSTR + (c >> 1)]) = t;
    }

    float o[8][4];
    #pragma unroll
    for (int nt = 0; nt < 8; ++nt)
        #pragma unroll
        for (int e = 0; e < 4; ++e) o[nt][e] = 0.f;
    float mrow[2] = {-1e30f, -1e30f};
    float lrow[2] = {0.f, 0.f};

    const int jmax = 2*qt + 1;

    float4 kreg[4], vreg[4];
    auto ldg_tile = [&](int jj) {
        const size_t rb = (size_t)jj * 64;
        #pragma unroll
        for (int p = 0; p < 4; ++p)
            kreg[p] = *reinterpret_cast<const float4*>(
                Kb + (rb + kr + p*16)*NHD + kc);
        #pragma unroll
        for (int g = 0; g < 4; ++g)
            vreg[g] = *reinterpret_cast<const float4*>(
                Vb + (rb + vkey)*NHD + vdg + g*4);
    };
    auto sts_tile = [&](int buf) {
        uint32_t* sK = sm + AOFF_K0 + buf * KTILE;   // [key][dw]
        __half* sVh = reinterpret_cast<__half*>(sm + AOFF_V0 + buf * KTILE); // [d][key] halves
        #pragma unroll
        for (int p = 0; p < 4; ++p) {
            uint2 t;
            t.x = pack_h2(kreg[p].x, kreg[p].y);
            t.y = pack_h2(kreg[p].z, kreg[p].w);
            *reinterpret_cast<uint2*>(&sK[(kr + p*16) * QSTR + (kc >> 1)]) = t;
        }
        #pragma unroll
        for (int g = 0; g < 4; ++g) {
            float f[4] = {vreg[g].x, vreg[g].y, vreg[g].z, vreg[g].w};
            #pragma unroll
            for (int e = 0; e < 4; ++e)
                sVh[(vdg + g*4 + e) * (QSTR*2) + vkey] = __float2half_rn(f[e]);
        }
    };

    // ---- prologue: tile 0 staged, tile 1 in regs ----
    ldg_tile(0);
    sts_tile(0);
    ldg_tile(1);          // jmax >= 1 always
    __syncthreads();

    for (int j = 0; j <= jmax; ++j) {
        const uint32_t* sK  = sm + AOFF_K0 + (j & 1) * KTILE;
        const uint32_t* sVt = sm + AOFF_V0 + (j & 1) * KTILE;

        if (j < jmax) {
            sts_tile((j + 1) & 1);
            if (j + 1 < jmax) ldg_tile(j + 2);
        }

        const bool active = (j*64 <= qt*128 + wm + 15);
        if (active) {
            // ---- S = Q @ K^T : 4 x k16 steps ----
            float s[8][4];
            #pragma unroll
            for (int nt = 0; nt < 8; ++nt)
                #pragma unroll
                for (int e = 0; e < 4; ++e) s[nt][e] = 0.f;

            #pragma unroll
            for (int kk = 0; kk < 4; ++kk) {
                const uint32_t* qp = &sQ[(wm + qrow) * QSTR + kk*8 + qcol];
                uint32_t a0 = qp[0], a1 = qp[8*QSTR], a2 = qp[4], a3 = qp[8*QSTR + 4];
                #pragma unroll
                for (int nt = 0; nt < 8; ++nt) {
                    const uint32_t* bp = &sK[(nt*8 + qrow) * QSTR + kk*8 + qcol];
                    mma_fp16(s[nt], a0, a1, a2, a3, bp[0], bp[4]);
                }
            }

            // ---- online softmax (per lane: 2 rows; fragment layout as before) ----
            const bool need_mask = (j >= 2*qt);
            #pragma unroll
            for (int r = 0; r < 2; ++r) {
                const int rowg = qt*128 + wm + qrow + r*8;
                float mx = -1e30f;
                #pragma unroll
                for (int nt = 0; nt < 8; ++nt) {
                    const int colg = j*64 + nt*8 + 2*qcol;
                    float v0 = s[nt][r*2 + 0] * SCALE_F;
                    float v1 = s[nt][r*2 + 1] * SCALE_F;
                    if (need_mask) {
                        if (colg     > rowg) v0 = -1e30f;
                        if (colg + 1 > rowg) v1 = -1e30f;
                    }
                    s[nt][r*2 + 0] = v0;
                    s[nt][r*2 + 1] = v1;
                    mx = fmaxf(mx, fmaxf(v0, v1));
                }
                mx = fmaxf(mx, __shfl_xor_sync(0xffffffffu, mx, 1));
                mx = fmaxf(mx, __shfl_xor_sync(0xffffffffu, mx, 2));
                const float mn    = fmaxf(mrow[r], mx);
                const float alpha = __expf(mrow[r] - mn);
                mrow[r] = mn;
                float ls = 0.f;
                #pragma unroll
                for (int nt = 0; nt < 8; ++nt) {
                    float p0 = __expf(s[nt][r*2 + 0] - mn);
                    float p1 = __expf(s[nt][r*2 + 1] - mn);
                    s[nt][r*2 + 0] = p0;
                    s[nt][r*2 + 1] = p1;
                    ls += p0 + p1;
                }
                ls += __shfl_xor_sync(0xffffffffu, ls, 1);
                ls += __shfl_xor_sync(0xffffffffu, ls, 2);
                lrow[r] = lrow[r]*alpha + ls;
                #pragma unroll
                for (int nt = 0; nt < 8; ++nt) {
                    o[nt][r*2 + 0] *= alpha;
                    o[nt][r*2 + 1] *= alpha;
                }
            }

            // ---- O += P @ V : P C-fragment -> A-fragment via register packs ----
            #pragma unroll
            for (int kk = 0; kk < 4; ++kk) {
                uint32_t a0 = pack_h2(s[2*kk  ][0], s[2*kk  ][1]);
                uint32_t a1 = pack_h2(s[2*kk  ][2], s[2*kk  ][3]);
                uint32_t a2 = pack_h2(s[2*kk+1][0], s[2*kk+1][1]);
                uint32_t a3 = pack_h2(s[2*kk+1][2], s[2*kk+1][3]);
                #pragma unroll
                for (int nt = 0; nt < 8; ++nt) {
                    const uint32_t* vp = &sVt[(nt*8 + qrow) * QSTR + kk*8 + qcol];
                    mma_fp16(o[nt], a0, a1, a2, a3, vp[0], vp[4]);
                }
            }
        }

        __syncthreads();   // compute(j) done AND STS(j+1) done
    }

    // ---- normalize + write [B,S,D] ----
    #pragma unroll
    for (int r = 0; r < 2; ++r) {
        const float inv = 1.0f / lrow[r];
        const int rowg = qt*128 + wm + qrow + r*8;
        #pragma unroll
        for (int nt = 0; nt < 8; ++nt) {
            const int col = h*NHD + nt*8 + 2*qcol;
            float2 ov;
            ov.x = o[nt][r*2 + 0] * inv;
            ov.y = o[nt][r*2 + 1] * inv;
            *reinterpret_cast<float2*>(
                O + ((size_t)b*NS + rowg)*ND + col) = ov;
        }
    }
}

// ---------------------------------------------------------------------------
extern "C" void kernel_launch(void* const* d_in, const int* in_sizes, int n_in,
                              void* d_out, int out_size)
{
    const float* x  = (const float*)d_in[0];
    const float* wq = (const float*)d_in[1];
    const float* bq = (const float*)d_in[2];
    const float* wk = (const float*)d_in[3];
    const float* bk = (const float*)d_in[4];
    const float* wv = (const float*)d_in[5];
    const float* bv = (const float*)d_in[6];
    const float* wo = (const float*)d_in[7];
    const float* bo = (const float*)d_in[8];
    float* out = (float*)d_out;

    float *q, *k, *v, *att;
    cudaGetSymbolAddress((void**)&q,   g_q);
    cudaGetSymbolAddress((void**)&k,   g_k);
    cudaGetSymbolAddress((void**)&v,   g_v);
    cudaGetSymbolAddress((void**)&att, g_att);

    static bool attr_done = false;
    if (!attr_done) {
        cudaFuncSetAttribute(attn_tc,
            cudaFuncAttributeMaxDynamicSharedMemorySize, ASMEM_WORDS * 4);
        attr_done = true;
    }

    dim3 qkv_grid(ND/128, NM/128, 3);   // (8, 32, 3) = 768 CTAs
    gemm_fp16k<true><<<qkv_grid, 256>>>(
        x, wq, bq, q, wk, bk, k, wv, bv, v);

    dim3 agrid(NS/128, NH, NB);         // (16, 16, 2)
    attn_tc<<<agrid, 256, ASMEM_WORDS * 4>>>(q, k, v, att);

    dim3 ogrid(ND/128, NM/128, 1);
    gemm_fp16k<false><<<ogrid, 256>>>(
        att, wo, bo, out, wo, bo, out, wo, bo, out);
}

// round 16
// speedup vs baseline: 2.1037x; 1.1238x over previous
#include <cuda_runtime.h>
#include <cuda_fp16.h>
#include <cstdint>

// Problem constants
#define NB 2
#define NS 2048
#define ND 1024
#define NH 16
#define NHD 64
#define NM (NB*NS)
#define SCALE_F 0.125f      // 64^-0.5

// Scratch (alloc-free rule: __device__ globals)
__device__ float g_q[NB*NH*NS*NHD];
__device__ float g_k[NB*NH*NS*NHD];
__device__ float g_v[NB*NH*NS*NHD];
__device__ float g_att[NB*NS*ND];

// ---------------------------------------------------------------------------
__device__ __forceinline__ uint32_t pack_h2(float lo, float hi) {
    __half2 h = __floats2half2_rn(lo, hi);
    return *reinterpret_cast<uint32_t*>(&h);
}

// fp16 m16n8k16, fp32 accumulate
__device__ __forceinline__ void mma_fp16(float c[4],
                                         uint32_t a0, uint32_t a1,
                                         uint32_t a2, uint32_t a3,
                                         uint32_t b0, uint32_t b1) {
    asm volatile(
        "mma.sync.aligned.m16n8k16.row.col.f32.f16.f16.f32 "
        "{%0,%1,%2,%3}, {%4,%5,%6,%7}, {%8,%9}, {%0,%1,%2,%3};"
        : "+f"(c[0]), "+f"(c[1]), "+f"(c[2]), "+f"(c[3])
        : "r"(a0), "r"(a1), "r"(a2), "r"(a3), "r"(b0), "r"(b1));
}

// ldmatrix x4: four 8x8 b16 matrices; lane l supplies row addr of matrix l>>3
__device__ __forceinline__ void ldm_x4(uint32_t& r0, uint32_t& r1,
                                       uint32_t& r2, uint32_t& r3,
                                       const uint32_t* p) {
    uint32_t addr = (uint32_t)__cvta_generic_to_shared(p);
    asm volatile(
        "ldmatrix.sync.aligned.m8n8.x4.shared.b16 {%0,%1,%2,%3}, [%4];"
        : "=r"(r0), "=r"(r1), "=r"(r2), "=r"(r3) : "r"(addr));
}

// ---------------------------------------------------------------------------
// fp16 m16n8k16 GEMM. R15: fragment loads via ldmatrix.x4 (12 per chunk vs
// 48 scalar LDS). Same words -> bit-identical numerics.
// grid.z selects (W, bias, C). SCATTER=true writes [B,H,S,HD].
// ---------------------------------------------------------------------------
#define GSTR 20   // word (half2) stride

template<bool SCATTER>
__global__ void __launch_bounds__(256)
gemm_fp16k(const float* __restrict__ A,
           const float* __restrict__ W0, const float* __restrict__ b0, float* __restrict__ C0,
           const float* __restrict__ W1, const float* __restrict__ b1, float* __restrict__ C1,
           const float* __restrict__ W2, const float* __restrict__ b2, float* __restrict__ C2)
{
    constexpr int N = ND, K = ND;
    constexpr int BK = 32;
    constexpr int NCHUNK = K / BK;

    __shared__ uint32_t sA[128 * GSTR];
    __shared__ uint32_t sB[128 * GSTR];

    const float* W;
    const float* bias;
    float* C;
    if (blockIdx.z == 0)      { W = W0; bias = b0; C = C0; }
    else if (blockIdx.z == 1) { W = W1; bias = b1; C = C1; }
    else                      { W = W2; bias = b2; C = C2; }

    const int tid  = threadIdx.x;
    const int wid  = tid >> 5;
    const int lane = tid & 31;
    const int m0   = blockIdx.y * 128;
    const int n0   = blockIdx.x * 128;

    const int wm = (wid >> 2) * 64;
    const int wn = (wid & 3)  * 32;

    const int nloc = tid & 127;
    const int kwb  = (tid >> 7) * 8;

    // ldmatrix per-lane address components
    const int a_row = wm + (lane & 7) + ((lane >> 3) & 1) * 8;
    const int a_kw  = (lane >> 4) * 4;
    const int b_row = wn + (lane & 7) + (lane >> 4) * 8;
    const int b_kw  = ((lane >> 3) & 1) * 4;

    float4 a_pf[4];
    float  b_pf[16];

    auto ldg_chunk = [&](int k0) {
        #pragma unroll
        for (int i = 0; i < 2; ++i) {
            int lin = tid + 256*i;
            int r = lin >> 2, j = lin & 3;
            const float* src = A + (size_t)(m0 + r) * K + k0 + j * 8;
            a_pf[i*2 + 0] = *reinterpret_cast<const float4*>(src);
            a_pf[i*2 + 1] = *reinterpret_cast<const float4*>(src + 4);
        }
        #pragma unroll
        for (int i = 0; i < 16; ++i)
            b_pf[i] = W[(size_t)(k0 + kwb*2 + i) * N + n0 + nloc];
    };
    auto sts_chunk = [&]() {
        #pragma unroll
        for (int i = 0; i < 2; ++i) {
            int lin = tid + 256*i;
            int r = lin >> 2, j = lin & 3;
            uint4 t;
            t.x = pack_h2(a_pf[i*2+0].x, a_pf[i*2+0].y);
            t.y = pack_h2(a_pf[i*2+0].z, a_pf[i*2+0].w);
            t.z = pack_h2(a_pf[i*2+1].x, a_pf[i*2+1].y);
            t.w = pack_h2(a_pf[i*2+1].z, a_pf[i*2+1].w);
            *reinterpret_cast<uint4*>(&sA[r * GSTR + j * 4]) = t;
        }
        {
            uint4 t0, t1;
            t0.x = pack_h2(b_pf[0],  b_pf[1]);
            t0.y = pack_h2(b_pf[2],  b_pf[3]);
            t0.z = pack_h2(b_pf[4],  b_pf[5]);
            t0.w = pack_h2(b_pf[6],  b_pf[7]);
            t1.x = pack_h2(b_pf[8],  b_pf[9]);
            t1.y = pack_h2(b_pf[10], b_pf[11]);
            t1.z = pack_h2(b_pf[12], b_pf[13]);
            t1.w = pack_h2(b_pf[14], b_pf[15]);
            *reinterpret_cast<uint4*>(&sB[nloc * GSTR + kwb])     = t0;
            *reinterpret_cast<uint4*>(&sB[nloc * GSTR + kwb + 4]) = t1;
        }
    };

    float acc[16][4];
    #pragma unroll
    for (int t = 0; t < 16; ++t)
        #pragma unroll
        for (int e = 0; e < 4; ++e) acc[t][e] = 0.f;

    const int qrow = lane >> 2;
    const int qcol = lane & 3;

    ldg_chunk(0);

    for (int c = 0; c < NCHUNK; ++c) {
        if (c > 0) __syncthreads();

        sts_chunk();

        if (c + 1 < NCHUNK) ldg_chunk((c + 1) * BK);

        __syncthreads();

        #pragma unroll
        for (int ks = 0; ks < 2; ++ks) {
            uint32_t af[4][4];
            #pragma unroll
            for (int i = 0; i < 4; ++i)
                ldm_x4(af[i][0], af[i][1], af[i][2], af[i][3],
                       &sA[(a_row + i*16) * GSTR + ks*8 + a_kw]);
            uint32_t bf[4][2];
            #pragma unroll
            for (int jp = 0; jp < 2; ++jp)
                ldm_x4(bf[jp*2][0], bf[jp*2][1], bf[jp*2+1][0], bf[jp*2+1][1],
                       &sB[(b_row + jp*16) * GSTR + ks*8 + b_kw]);
            #pragma unroll
            for (int i = 0; i < 4; ++i)
                #pragma unroll
                for (int j = 0; j < 4; ++j)
                    mma_fp16(acc[i*4 + j],
                             af[i][0], af[i][1], af[i][2], af[i][3],
                             bf[j][0], bf[j][1]);
        }
    }

    #pragma unroll
    for (int i = 0; i < 4; ++i) {
        #pragma unroll
        for (int j = 0; j < 4; ++j) {
            const float* a4 = acc[i*4 + j];
            const int colg  = n0 + wn + j*8 + 2*qcol;
            const float2 bv = *reinterpret_cast<const float2*>(bias + colg);
            #pragma unroll
            for (int half = 0; half < 2; ++half) {
                const int m = m0 + wm + i*16 + qrow + half*8;
                float2 o;
                o.x = a4[half*2 + 0] + bv.x;
                o.y = a4[half*2 + 1] + bv.y;
                size_t idx;
                if (SCATTER) {
                    const int b = m >> 11;
                    const int s = m & (NS - 1);
                    const int h = colg >> 6;
                    const int hd = colg & 63;
                    idx = (((size_t)(b*NH + h))*NS + s)*NHD + hd;
                } else {
                    idx = (size_t)m * N + colg;
                }
                *reinterpret_cast<float2*>(C + idx) = o;
            }
        }
    }
}

// ---------------------------------------------------------------------------
// fp16 tensor-core flash attention, causal. R15: fragment loads via ldmatrix.
// Otherwise identical to R14 (P register-pack chaining, double-buffered K/V,
// one barrier per iteration). smem 55296 B.
// ---------------------------------------------------------------------------
#define QSTR   36               // half2-word stride
#define AOFF_Q 0                // 128*36 = 4608 words
#define KTILE  (64*36)          // 2304 words
#define AOFF_K0 4608
#define AOFF_V0 9216
#define ASMEM_WORDS 13824       // *4 = 55296 B

__global__ void __launch_bounds__(256, 2)
attn_tc(const float* __restrict__ Q, const float* __restrict__ K,
        const float* __restrict__ V, float* __restrict__ O)
{
    extern __shared__ uint32_t sm[];
    uint32_t* sQ = sm + AOFF_Q;

    const int tid  = threadIdx.x;
    const int wid  = tid >> 5;
    const int lane = tid & 31;
    const int qrow = lane >> 2;   // 0..7
    const int qcol = lane & 3;    // 0..3
    const int wm   = wid * 16;

    const int qt = (NS/128 - 1) - blockIdx.x;   // largest-work tiles first
    const int h  = blockIdx.y;
    const int b  = blockIdx.z;
    const int bh = b*NH + h;

    const float* Qb = Q + (size_t)bh * NS * NHD;
    const float* Kb = K + (size_t)bh * NS * NHD;
    const float* Vb = V + (size_t)bh * NS * NHD;

    const int kr = tid >> 4;         // 0..15
    const int kc = (tid & 15) * 4;   // 0..60
    const int vkey = tid & 63;
    const int vdg  = (tid >> 6) * 16;

    // ldmatrix per-lane address components
    const int qa_row = wm + (lane & 7) + ((lane >> 3) & 1) * 8;   // A side (Q)
    const int qa_kw  = (lane >> 4) * 4;
    const int kb_row = (lane & 7) + (lane >> 4) * 8;              // B side (K/V)
    const int kb_kw  = ((lane >> 3) & 1) * 4;

    // ---- load Q tile as half2 words, [row][dw] ----
    #pragma unroll
    for (int p = 0; p < 8; ++p) {
        int lin = tid + 256*p;
        int r = lin >> 4, c = (lin & 15) * 4;
        float4 qv = *reinterpret_cast<const float4*>(
            Qb + (size_t)(qt*128 + r)*NHD + c);
        uint2 t;
        t.x = pack_h2(qv.x, qv.y);
        t.y = pack_h2(qv.z, qv.w);
        *reinterpret_cast<uint2*>(&sQ[r * QSTR + (c >> 1)]) = t;
    }

    float o[8][4];
    #pragma unroll
    for (int nt = 0; nt < 8; ++nt)
        #pragma unroll
        for (int e = 0; e < 4; ++e) o[nt][e] = 0.f;
    float mrow[2] = {-1e30f, -1e30f};
    float lrow[2] = {0.f, 0.f};

    const int jmax = 2*qt + 1;

    float4 kreg[4], vreg[4];
    auto ldg_tile = [&](int jj) {
        const size_t rb = (size_t)jj * 64;
        #pragma unroll
        for (int p = 0; p < 4; ++p)
            kreg[p] = *reinterpret_cast<const float4*>(
                Kb + (rb + kr + p*16)*NHD + kc);
        #pragma unroll
        for (int g = 0; g < 4; ++g)
            vreg[g] = *reinterpret_cast<const float4*>(
                Vb + (rb + vkey)*NHD + vdg + g*4);
    };
    auto sts_tile = [&](int buf) {
        uint32_t* sK = sm + AOFF_K0 + buf * KTILE;   // [key][dw]
        __half* sVh = reinterpret_cast<__half*>(sm + AOFF_V0 + buf * KTILE); // [d][key]
        #pragma unroll
        for (int p = 0; p < 4; ++p) {
            uint2 t;
            t.x = pack_h2(kreg[p].x, kreg[p].y);
            t.y = pack_h2(kreg[p].z, kreg[p].w);
            *reinterpret_cast<uint2*>(&sK[(kr + p*16) * QSTR + (kc >> 1)]) = t;
        }
        #pragma unroll
        for (int g = 0; g < 4; ++g) {
            float f[4] = {vreg[g].x, vreg[g].y, vreg[g].z, vreg[g].w};
            #pragma unroll
            for (int e = 0; e < 4; ++e)
                sVh[(vdg + g*4 + e) * (QSTR*2) + vkey] = __float2half_rn(f[e]);
        }
    };

    // ---- prologue: tile 0 staged, tile 1 in regs ----
    ldg_tile(0);
    sts_tile(0);
    ldg_tile(1);          // jmax >= 1 always
    __syncthreads();

    for (int j = 0; j <= jmax; ++j) {
        const uint32_t* sK  = sm + AOFF_K0 + (j & 1) * KTILE;
        const uint32_t* sVt = sm + AOFF_V0 + (j & 1) * KTILE;

        if (j < jmax) {
            sts_tile((j + 1) & 1);
            if (j + 1 < jmax) ldg_tile(j + 2);
        }

        const bool active = (j*64 <= qt*128 + wm + 15);
        if (active) {
            // ---- S = Q @ K^T : 4 x k16 steps, ldmatrix operands ----
            float s[8][4];
            #pragma unroll
            for (int nt = 0; nt < 8; ++nt)
                #pragma unroll
                for (int e = 0; e < 4; ++e) s[nt][e] = 0.f;

            #pragma unroll
            for (int kk = 0; kk < 4; ++kk) {
                uint32_t a0, a1, a2, a3;
                ldm_x4(a0, a1, a2, a3, &sQ[qa_row * QSTR + kk*8 + qa_kw]);
                uint32_t bf[8][2];
                #pragma unroll
                for (int ntp = 0; ntp < 4; ++ntp)
                    ldm_x4(bf[ntp*2][0], bf[ntp*2][1], bf[ntp*2+1][0], bf[ntp*2+1][1],
                           &sK[(kb_row + ntp*16) * QSTR + kk*8 + kb_kw]);
                #pragma unroll
                for (int nt = 0; nt < 8; ++nt)
                    mma_fp16(s[nt], a0, a1, a2, a3, bf[nt][0], bf[nt][1]);
            }

            // ---- online softmax (per lane: 2 rows) ----
            const bool need_mask = (j >= 2*qt);
            #pragma unroll
            for (int r = 0; r < 2; ++r) {
                const int rowg = qt*128 + wm + qrow + r*8;
                float mx = -1e30f;
                #pragma unroll
                for (int nt = 0; nt < 8; ++nt) {
                    const int colg = j*64 + nt*8 + 2*qcol;
                    float v0 = s[nt][r*2 + 0] * SCALE_F;
                    float v1 = s[nt][r*2 + 1] * SCALE_F;
                    if (need_mask) {
                        if (colg     > rowg) v0 = -1e30f;
                        if (colg + 1 > rowg) v1 = -1e30f;
                    }
                    s[nt][r*2 + 0] = v0;
                    s[nt][r*2 + 1] = v1;
                    mx = fmaxf(mx, fmaxf(v0, v1));
                }
                mx = fmaxf(mx, __shfl_xor_sync(0xffffffffu, mx, 1));
                mx = fmaxf(mx, __shfl_xor_sync(0xffffffffu, mx, 2));
                const float mn    = fmaxf(mrow[r], mx);
                const float alpha = __expf(mrow[r] - mn);
                mrow[r] = mn;
                float ls = 0.f;
                #pragma unroll
                for (int nt = 0; nt < 8; ++nt) {
                    float p0 = __expf(s[nt][r*2 + 0] - mn);
                    float p1 = __expf(s[nt][r*2 + 1] - mn);
                    s[nt][r*2 + 0] = p0;
                    s[nt][r*2 + 1] = p1;
                    ls += p0 + p1;
                }
                ls += __shfl_xor_sync(0xffffffffu, ls, 1);
                ls += __shfl_xor_sync(0xffffffffu, ls, 2);
                lrow[r] = lrow[r]*alpha + ls;
                #pragma unroll
                for (int nt = 0; nt < 8; ++nt) {
                    o[nt][r*2 + 0] *= alpha;
                    o[nt][r*2 + 1] *= alpha;
                }
            }

            // ---- O += P @ V : P via register packs, V via ldmatrix ----
            #pragma unroll
            for (int kk = 0; kk < 4; ++kk) {
                uint32_t a0 = pack_h2(s[2*kk  ][0], s[2*kk  ][1]);
                uint32_t a1 = pack_h2(s[2*kk  ][2], s[2*kk  ][3]);
                uint32_t a2 = pack_h2(s[2*kk+1][0], s[2*kk+1][1]);
                uint32_t a3 = pack_h2(s[2*kk+1][2], s[2*kk+1][3]);
                uint32_t vf[8][2];
                #pragma unroll
                for (int ntp = 0; ntp < 4; ++ntp)
                    ldm_x4(vf[ntp*2][0], vf[ntp*2][1], vf[ntp*2+1][0], vf[ntp*2+1][1],
                           &sVt[(kb_row + ntp*16) * QSTR + kk*8 + kb_kw]);
                #pragma unroll
                for (int nt = 0; nt < 8; ++nt)
                    mma_fp16(o[nt], a0, a1, a2, a3, vf[nt][0], vf[nt][1]);
            }
        }

        __syncthreads();   // compute(j) done AND STS(j+1) done
    }

    // ---- normalize + write [B,S,D] ----
    #pragma unroll
    for (int r = 0; r < 2; ++r) {
        const float inv = 1.0f / lrow[r];
        const int rowg = qt*128 + wm + qrow + r*8;
        #pragma unroll
        for (int nt = 0; nt < 8; ++nt) {
            const int col = h*NHD + nt*8 + 2*qcol;
            float2 ov;
            ov.x = o[nt][r*2 + 0] * inv;
            ov.y = o[nt][r*2 + 1] * inv;
            *reinterpret_cast<float2*>(
                O + ((size_t)b*NS + rowg)*ND + col) = ov;
        }
    }
}

// ---------------------------------------------------------------------------
extern "C" void kernel_launch(void* const* d_in, const int* in_sizes, int n_in,
                              void* d_out, int out_size)
{
    const float* x  = (const float*)d_in[0];
    const float* wq = (const float*)d_in[1];
    const float* bq = (const float*)d_in[2];
    const float* wk = (const float*)d_in[3];
    const float* bk = (const float*)d_in[4];
    const float* wv = (const float*)d_in[5];
    const float* bv = (const float*)d_in[6];
    const float* wo = (const float*)d_in[7];
    const float* bo = (const float*)d_in[8];
    float* out = (float*)d_out;

    float *q, *k, *v, *att;
    cudaGetSymbolAddress((void**)&q,   g_q);
    cudaGetSymbolAddress((void**)&k,   g_k);
    cudaGetSymbolAddress((void**)&v,   g_v);
    cudaGetSymbolAddress((void**)&att, g_att);

    static bool attr_done = false;
    if (!attr_done) {
        cudaFuncSetAttribute(attn_tc,
            cudaFuncAttributeMaxDynamicSharedMemorySize, ASMEM_WORDS * 4);
        attr_done = true;
    }

    dim3 qkv_grid(ND/128, NM/128, 3);   // (8, 32, 3) = 768 CTAs
    gemm_fp16k<true><<<qkv_grid, 256>>>(
        x, wq, bq, q, wk, bk, k, wv, bv, v);

    dim3 agrid(NS/128, NH, NB);         // (16, 16, 2)
    attn_tc<<<agrid, 256, ASMEM_WORDS * 4>>>(q, k, v, att);

    dim3 ogrid(ND/128, NM/128, 1);
    gemm_fp16k<false><<<ogrid, 256>>>(
        att, wo, bo, out, wo, bo, out, wo, bo, out);
}

// round 17
// speedup vs baseline: 2.1876x; 1.0399x over previous
#include <cuda_runtime.h>
#include <cuda_fp16.h>
#include <cstdint>

// Problem constants
#define NB 2
#define NS 2048
#define ND 1024
#define NH 16
#define NHD 64
#define NM (NB*NS)
#define SCALE_F 0.125f      // 64^-0.5

// Scratch (alloc-free rule: __device__ globals)
__device__ float g_q[NB*NH*NS*NHD];
__device__ float g_k[NB*NH*NS*NHD];
__device__ float g_v[NB*NH*NS*NHD];
__device__ float g_att[NB*NS*ND];

// ---------------------------------------------------------------------------
__device__ __forceinline__ uint32_t pack_h2(float lo, float hi) {
    __half2 h = __floats2half2_rn(lo, hi);
    return *reinterpret_cast<uint32_t*>(&h);
}

__device__ __forceinline__ float ex2(float x) {
    float y;
    asm("ex2.approx.f32 %0, %1;" : "=f"(y) : "f"(x));
    return y;
}

// fp16 m16n8k16, fp32 accumulate
__device__ __forceinline__ void mma_fp16(float c[4],
                                         uint32_t a0, uint32_t a1,
                                         uint32_t a2, uint32_t a3,
                                         uint32_t b0, uint32_t b1) {
    asm volatile(
        "mma.sync.aligned.m16n8k16.row.col.f32.f16.f16.f32 "
        "{%0,%1,%2,%3}, {%4,%5,%6,%7}, {%8,%9}, {%0,%1,%2,%3};"
        : "+f"(c[0]), "+f"(c[1]), "+f"(c[2]), "+f"(c[3])
        : "r"(a0), "r"(a1), "r"(a2), "r"(a3), "r"(b0), "r"(b1));
}

__device__ __forceinline__ void ldm_x4(uint32_t& r0, uint32_t& r1,
                                       uint32_t& r2, uint32_t& r3,
                                       const uint32_t* p) {
    uint32_t addr = (uint32_t)__cvta_generic_to_shared(p);
    asm volatile(
        "ldmatrix.sync.aligned.m8n8.x4.shared.b16 {%0,%1,%2,%3}, [%4];"
        : "=r"(r0), "=r"(r1), "=r"(r2), "=r"(r3) : "r"(addr));
}

__device__ __forceinline__ void ldm_x4_t(uint32_t& r0, uint32_t& r1,
                                         uint32_t& r2, uint32_t& r3,
                                         const uint32_t* p) {
    uint32_t addr = (uint32_t)__cvta_generic_to_shared(p);
    asm volatile(
        "ldmatrix.sync.aligned.m8n8.x4.trans.shared.b16 {%0,%1,%2,%3}, [%4];"
        : "=r"(r0), "=r"(r1), "=r"(r2), "=r"(r3) : "r"(addr));
}

// ---------------------------------------------------------------------------
// fp16 m16n8k16 GEMM — UNCHANGED from R15 (passing, 121us QKV).
// ---------------------------------------------------------------------------
#define GSTR 20   // word (half2) stride

template<bool SCATTER>
__global__ void __launch_bounds__(256)
gemm_fp16k(const float* __restrict__ A,
           const float* __restrict__ W0, const float* __restrict__ b0, float* __restrict__ C0,
           const float* __restrict__ W1, const float* __restrict__ b1, float* __restrict__ C1,
           const float* __restrict__ W2, const float* __restrict__ b2, float* __restrict__ C2)
{
    constexpr int N = ND, K = ND;
    constexpr int BK = 32;
    constexpr int NCHUNK = K / BK;

    __shared__ uint32_t sA[128 * GSTR];
    __shared__ uint32_t sB[128 * GSTR];

    const float* W;
    const float* bias;
    float* C;
    if (blockIdx.z == 0)      { W = W0; bias = b0; C = C0; }
    else if (blockIdx.z == 1) { W = W1; bias = b1; C = C1; }
    else                      { W = W2; bias = b2; C = C2; }

    const int tid  = threadIdx.x;
    const int wid  = tid >> 5;
    const int lane = tid & 31;
    const int m0   = blockIdx.y * 128;
    const int n0   = blockIdx.x * 128;

    const int wm = (wid >> 2) * 64;
    const int wn = (wid & 3)  * 32;

    const int nloc = tid & 127;
    const int kwb  = (tid >> 7) * 8;

    const int a_row = wm + (lane & 7) + ((lane >> 3) & 1) * 8;
    const int a_kw  = (lane >> 4) * 4;
    const int b_row = wn + (lane & 7) + (lane >> 4) * 8;
    const int b_kw  = ((lane >> 3) & 1) * 4;

    float4 a_pf[4];
    float  b_pf[16];

    auto ldg_chunk = [&](int k0) {
        #pragma unroll
        for (int i = 0; i < 2; ++i) {
            int lin = tid + 256*i;
            int r = lin >> 2, j = lin & 3;
            const float* src = A + (size_t)(m0 + r) * K + k0 + j * 8;
            a_pf[i*2 + 0] = *reinterpret_cast<const float4*>(src);
            a_pf[i*2 + 1] = *reinterpret_cast<const float4*>(src + 4);
        }
        #pragma unroll
        for (int i = 0; i < 16; ++i)
            b_pf[i] = W[(size_t)(k0 + kwb*2 + i) * N + n0 + nloc];
    };
    auto sts_chunk = [&]() {
        #pragma unroll
        for (int i = 0; i < 2; ++i) {
            int lin = tid + 256*i;
            int r = lin >> 2, j = lin & 3;
            uint4 t;
            t.x = pack_h2(a_pf[i*2+0].x, a_pf[i*2+0].y);
            t.y = pack_h2(a_pf[i*2+0].z, a_pf[i*2+0].w);
            t.z = pack_h2(a_pf[i*2+1].x, a_pf[i*2+1].y);
            t.w = pack_h2(a_pf[i*2+1].z, a_pf[i*2+1].w);
            *reinterpret_cast<uint4*>(&sA[r * GSTR + j * 4]) = t;
        }
        {
            uint4 t0, t1;
            t0.x = pack_h2(b_pf[0],  b_pf[1]);
            t0.y = pack_h2(b_pf[2],  b_pf[3]);
            t0.z = pack_h2(b_pf[4],  b_pf[5]);
            t0.w = pack_h2(b_pf[6],  b_pf[7]);
            t1.x = pack_h2(b_pf[8],  b_pf[9]);
            t1.y = pack_h2(b_pf[10], b_pf[11]);
            t1.z = pack_h2(b_pf[12], b_pf[13]);
            t1.w = pack_h2(b_pf[14], b_pf[15]);
            *reinterpret_cast<uint4*>(&sB[nloc * GSTR + kwb])     = t0;
            *reinterpret_cast<uint4*>(&sB[nloc * GSTR + kwb + 4]) = t1;
        }
    };

    float acc[16][4];
    #pragma unroll
    for (int t = 0; t < 16; ++t)
        #pragma unroll
        for (int e = 0; e < 4; ++e) acc[t][e] = 0.f;

    const int qrow = lane >> 2;
    const int qcol = lane & 3;

    ldg_chunk(0);

    for (int c = 0; c < NCHUNK; ++c) {
        if (c > 0) __syncthreads();

        sts_chunk();

        if (c + 1 < NCHUNK) ldg_chunk((c + 1) * BK);

        __syncthreads();

        #pragma unroll
        for (int ks = 0; ks < 2; ++ks) {
            uint32_t af[4][4];
            #pragma unroll
            for (int i = 0; i < 4; ++i)
                ldm_x4(af[i][0], af[i][1], af[i][2], af[i][3],
                       &sA[(a_row + i*16) * GSTR + ks*8 + a_kw]);
            uint32_t bf[4][2];
            #pragma unroll
            for (int jp = 0; jp < 2; ++jp)
                ldm_x4(bf[jp*2][0], bf[jp*2][1], bf[jp*2+1][0], bf[jp*2+1][1],
                       &sB[(b_row + jp*16) * GSTR + ks*8 + b_kw]);
            #pragma unroll
            for (int i = 0; i < 4; ++i)
                #pragma unroll
                for (int j = 0; j < 4; ++j)
                    mma_fp16(acc[i*4 + j],
                             af[i][0], af[i][1], af[i][2], af[i][3],
                             bf[j][0], bf[j][1]);
        }
    }

    #pragma unroll
    for (int i = 0; i < 4; ++i) {
        #pragma unroll
        for (int j = 0; j < 4; ++j) {
            const float* a4 = acc[i*4 + j];
            const int colg  = n0 + wn + j*8 + 2*qcol;
            const float2 bv = *reinterpret_cast<const float2*>(bias + colg);
            #pragma unroll
            for (int half = 0; half < 2; ++half) {
                const int m = m0 + wm + i*16 + qrow + half*8;
                float2 o;
                o.x = a4[half*2 + 0] + bv.x;
                o.y = a4[half*2 + 1] + bv.y;
                size_t idx;
                if (SCATTER) {
                    const int b = m >> 11;
                    const int s = m & (NS - 1);
                    const int h = colg >> 6;
                    const int hd = colg & 63;
                    idx = (((size_t)(b*NH + h))*NS + s)*NHD + hd;
                } else {
                    idx = (size_t)m * N + colg;
                }
                *reinterpret_cast<float2*>(C + idx) = o;
            }
        }
    }
}

// ---------------------------------------------------------------------------
// fp16 flash attention, causal. R16:
//  - scale (SCALE*log2e) folded into Q staging; softmax in base-2 (ex2.approx)
//  - V stored [key][dw] with vectorized uint2 STS; PV B-frags via ldmatrix.trans
// Double-buffered K/V, one barrier/iter. smem 55296 B.
// ---------------------------------------------------------------------------
#define QSTR   36               // half2-word stride
#define AOFF_Q 0                // 128*36 = 4608 words
#define KTILE  (64*36)          // 2304 words
#define AOFF_K0 4608
#define AOFF_V0 9216
#define ASMEM_WORDS 13824       // *4 = 55296 B
#define QK_SCALE (0.125f * 1.44269504088896f)   // SCALE * log2(e)

__global__ void __launch_bounds__(256, 2)
attn_tc(const float* __restrict__ Q, const float* __restrict__ K,
        const float* __restrict__ V, float* __restrict__ O)
{
    extern __shared__ uint32_t sm[];
    uint32_t* sQ = sm + AOFF_Q;

    const int tid  = threadIdx.x;
    const int wid  = tid >> 5;
    const int lane = tid & 31;
    const int qrow = lane >> 2;   // 0..7
    const int qcol = lane & 3;    // 0..3
    const int wm   = wid * 16;

    const int qt = (NS/128 - 1) - blockIdx.x;   // largest-work tiles first
    const int h  = blockIdx.y;
    const int b  = blockIdx.z;
    const int bh = b*NH + h;

    const float* Qb = Q + (size_t)bh * NS * NHD;
    const float* Kb = K + (size_t)bh * NS * NHD;
    const float* Vb = V + (size_t)bh * NS * NHD;

    const int kr = tid >> 4;         // 0..15
    const int kc = (tid & 15) * 4;   // 0..60
    const int vkey = tid & 63;
    const int vdg  = (tid >> 6) * 16;

    // ldmatrix per-lane address components
    const int qa_row = wm + (lane & 7) + ((lane >> 3) & 1) * 8;   // A side (Q)
    const int qa_kw  = (lane >> 4) * 4;
    const int kb_row = (lane & 7) + (lane >> 4) * 8;              // B side (K)
    const int kb_kw  = ((lane >> 3) & 1) * 4;
    const int vt_row = (lane & 7) + ((lane >> 3) & 1) * 8;        // B side (V, trans)
    const int vt_kw  = (lane >> 4) * 4;

    // ---- load Q tile as half2 words, scaled by QK_SCALE ----
    #pragma unroll
    for (int p = 0; p < 8; ++p) {
        int lin = tid + 256*p;
        int r = lin >> 4, c = (lin & 15) * 4;
        float4 qv = *reinterpret_cast<const float4*>(
            Qb + (size_t)(qt*128 + r)*NHD + c);
        uint2 t;
        t.x = pack_h2(qv.x * QK_SCALE, qv.y * QK_SCALE);
        t.y = pack_h2(qv.z * QK_SCALE, qv.w * QK_SCALE);
        *reinterpret_cast<uint2*>(&sQ[r * QSTR + (c >> 1)]) = t;
    }

    float o[8][4];
    #pragma unroll
    for (int nt = 0; nt < 8; ++nt)
        #pragma unroll
        for (int e = 0; e < 4; ++e) o[nt][e] = 0.f;
    float mrow[2] = {-1e30f, -1e30f};
    float lrow[2] = {0.f, 0.f};

    const int jmax = 2*qt + 1;

    float4 kreg[4], vreg[4];
    auto ldg_tile = [&](int jj) {
        const size_t rb = (size_t)jj * 64;
        #pragma unroll
        for (int p = 0; p < 4; ++p)
            kreg[p] = *reinterpret_cast<const float4*>(
                Kb + (rb + kr + p*16)*NHD + kc);
        #pragma unroll
        for (int g = 0; g < 4; ++g)
            vreg[g] = *reinterpret_cast<const float4*>(
                Vb + (rb + vkey)*NHD + vdg + g*4);
    };
    auto sts_tile = [&](int buf) {
        uint32_t* sK = sm + AOFF_K0 + buf * KTILE;   // [key][dw]
        uint32_t* sV = sm + AOFF_V0 + buf * KTILE;   // [key][dw] (row-major!)
        #pragma unroll
        for (int p = 0; p < 4; ++p) {
            uint2 t;
            t.x = pack_h2(kreg[p].x, kreg[p].y);
            t.y = pack_h2(kreg[p].z, kreg[p].w);
            *reinterpret_cast<uint2*>(&sK[(kr + p*16) * QSTR + (kc >> 1)]) = t;
        }
        #pragma unroll
        for (int g = 0; g < 4; ++g) {
            uint2 t;
            t.x = pack_h2(vreg[g].x, vreg[g].y);
            t.y = pack_h2(vreg[g].z, vreg[g].w);
            *reinterpret_cast<uint2*>(&sV[vkey * QSTR + (vdg >> 1) + g*2]) = t;
        }
    };

    // ---- prologue: tile 0 staged, tile 1 in regs ----
    ldg_tile(0);
    sts_tile(0);
    ldg_tile(1);          // jmax >= 1 always
    __syncthreads();

    for (int j = 0; j <= jmax; ++j) {
        const uint32_t* sK = sm + AOFF_K0 + (j & 1) * KTILE;
        const uint32_t* sV = sm + AOFF_V0 + (j & 1) * KTILE;

        if (j < jmax) {
            sts_tile((j + 1) & 1);
            if (j + 1 < jmax) ldg_tile(j + 2);
        }

        const bool active = (j*64 <= qt*128 + wm + 15);
        if (active) {
            // ---- S = (Q*scale*log2e) @ K^T : 4 x k16 steps ----
            float s[8][4];
            #pragma unroll
            for (int nt = 0; nt < 8; ++nt)
                #pragma unroll
                for (int e = 0; e < 4; ++e) s[nt][e] = 0.f;

            #pragma unroll
            for (int kk = 0; kk < 4; ++kk) {
                uint32_t a0, a1, a2, a3;
                ldm_x4(a0, a1, a2, a3, &sQ[qa_row * QSTR + kk*8 + qa_kw]);
                uint32_t bf[8][2];
                #pragma unroll
                for (int ntp = 0; ntp < 4; ++ntp)
                    ldm_x4(bf[ntp*2][0], bf[ntp*2][1], bf[ntp*2+1][0], bf[ntp*2+1][1],
                           &sK[(kb_row + ntp*16) * QSTR + kk*8 + kb_kw]);
                #pragma unroll
                for (int nt = 0; nt < 8; ++nt)
                    mma_fp16(s[nt], a0, a1, a2, a3, bf[nt][0], bf[nt][1]);
            }

            // ---- online softmax in base-2 (per lane: 2 rows) ----
            const bool need_mask = (j >= 2*qt);
            #pragma unroll
            for (int r = 0; r < 2; ++r) {
                const int rowg = qt*128 + wm + qrow + r*8;
                float mx = -1e30f;
                #pragma unroll
                for (int nt = 0; nt < 8; ++nt) {
                    if (need_mask) {
                        const int colg = j*64 + nt*8 + 2*qcol;
                        if (colg     > rowg) s[nt][r*2 + 0] = -1e30f;
                        if (colg + 1 > rowg) s[nt][r*2 + 1] = -1e30f;
                    }
                    mx = fmaxf(mx, fmaxf(s[nt][r*2 + 0], s[nt][r*2 + 1]));
                }
                mx = fmaxf(mx, __shfl_xor_sync(0xffffffffu, mx, 1));
                mx = fmaxf(mx, __shfl_xor_sync(0xffffffffu, mx, 2));
                const float mn    = fmaxf(mrow[r], mx);
                const float alpha = ex2(mrow[r] - mn);
                mrow[r] = mn;
                float ls = 0.f;
                #pragma unroll
                for (int nt = 0; nt < 8; ++nt) {
                    float p0 = ex2(s[nt][r*2 + 0] - mn);
                    float p1 = ex2(s[nt][r*2 + 1] - mn);
                    s[nt][r*2 + 0] = p0;
                    s[nt][r*2 + 1] = p1;
                    ls += p0 + p1;
                }
                ls += __shfl_xor_sync(0xffffffffu, ls, 1);
                ls += __shfl_xor_sync(0xffffffffu, ls, 2);
                lrow[r] = lrow[r]*alpha + ls;
                #pragma unroll
                for (int nt = 0; nt < 8; ++nt) {
                    o[nt][r*2 + 0] *= alpha;
                    o[nt][r*2 + 1] *= alpha;
                }
            }

            // ---- O += P @ V : P register packs, V^T via ldmatrix.trans ----
            #pragma unroll
            for (int kk = 0; kk < 4; ++kk) {
                uint32_t a0 = pack_h2(s[2*kk  ][0], s[2*kk  ][1]);
                uint32_t a1 = pack_h2(s[2*kk  ][2], s[2*kk  ][3]);
                uint32_t a2 = pack_h2(s[2*kk+1][0], s[2*kk+1][1]);
                uint32_t a3 = pack_h2(s[2*kk+1][2], s[2*kk+1][3]);
                uint32_t vf[8][2];
                #pragma unroll
                for (int ntp = 0; ntp < 4; ++ntp)
                    ldm_x4_t(vf[ntp*2][0], vf[ntp*2][1], vf[ntp*2+1][0], vf[ntp*2+1][1],
                             &sV[(kk*16 + vt_row) * QSTR + ntp*8 + vt_kw]);
                #pragma unroll
                for (int nt = 0; nt < 8; ++nt)
                    mma_fp16(o[nt], a0, a1, a2, a3, vf[nt][0], vf[nt][1]);
            }
        }

        __syncthreads();   // compute(j) done AND STS(j+1) done
    }

    // ---- normalize + write [B,S,D] ----
    #pragma unroll
    for (int r = 0; r < 2; ++r) {
        const float inv = 1.0f / lrow[r];
        const int rowg = qt*128 + wm + qrow + r*8;
        #pragma unroll
        for (int nt = 0; nt < 8; ++nt) {
            const int col = h*NHD + nt*8 + 2*qcol;
            float2 ov;
            ov.x = o[nt][r*2 + 0] * inv;
            ov.y = o[nt][r*2 + 1] * inv;
            *reinterpret_cast<float2*>(
                O + ((size_t)b*NS + rowg)*ND + col) = ov;
        }
    }
}

// ---------------------------------------------------------------------------
extern "C" void kernel_launch(void* const* d_in, const int* in_sizes, int n_in,
                              void* d_out, int out_size)
{
    const float* x  = (const float*)d_in[0];
    const float* wq = (const float*)d_in[1];
    const float* bq = (const float*)d_in[2];
    const float* wk = (const float*)d_in[3];
    const float* bk = (const float*)d_in[4];
    const float* wv = (const float*)d_in[5];
    const float* bv = (const float*)d_in[6];
    const float* wo = (const float*)d_in[7];
    const float* bo = (const float*)d_in[8];
    float* out = (float*)d_out;

    float *q, *k, *v, *att;
    cudaGetSymbolAddress((void**)&q,   g_q);
    cudaGetSymbolAddress((void**)&k,   g_k);
    cudaGetSymbolAddress((void**)&v,   g_v);
    cudaGetSymbolAddress((void**)&att, g_att);

    static bool attr_done = false;
    if (!attr_done) {
        cudaFuncSetAttribute(attn_tc,
            cudaFuncAttributeMaxDynamicSharedMemorySize, ASMEM_WORDS * 4);
        attr_done = true;
    }

    dim3 qkv_grid(ND/128, NM/128, 3);   // (8, 32, 3) = 768 CTAs
    gemm_fp16k<true><<<qkv_grid, 256>>>(
        x, wq, bq, q, wk, bk, k, wv, bv, v);

    dim3 agrid(NS/128, NH, NB);         // (16, 16, 2)
    attn_tc<<<agrid, 256, ASMEM_WORDS * 4>>>(q, k, v, att);

    dim3 ogrid(ND/128, NM/128, 1);
    gemm_fp16k<false><<<ogrid, 256>>>(
        att, wo, bo, out, wo, bo, out, wo, bo, out);
}